// round 6
// baseline (speedup 1.0000x reference)
#include <cuda_runtime.h>
#include <cuda_bf16.h>
#include <math.h>

// Problem constants
#define BB 2
#define SS 2048
#define DD 1024
#define HH 16
#define DKK 64
#define MM (BB * SS)

// ---------------------------------------------------------------------------
// Scratch (device globals)
// ---------------------------------------------------------------------------
__device__ float g_Q[BB * HH * SS * DKK];   // [B,H,S,DK]  tf32-rounded
__device__ float g_K[BB * HH * SS * DKK];
__device__ float g_V[BB * HH * SS * DKK];
__device__ float g_Ctx[BB * SS * DD];       // [B,S,D]     tf32-rounded
__device__ float g_w[4][DD * DD];           // tf32-rounded weights q,k,v,o

// ---------------------------------------------------------------------------
// helpers
// ---------------------------------------------------------------------------
__device__ __forceinline__ unsigned f2tf32(float x) {
    unsigned y;
    asm("cvt.rna.tf32.f32 %0, %1;" : "=r"(y) : "f"(x));
    return y;
}
__device__ __forceinline__ float f2tf32f(float x) { return __uint_as_float(f2tf32(x)); }

__device__ __forceinline__ float ex2(float x) {
    float y;
    asm("ex2.approx.f32 %0, %1;" : "=f"(y) : "f"(x));
    return y;
}

__device__ __forceinline__ void mma_tf32(float* c, const unsigned* a, const unsigned* b) {
    asm volatile("mma.sync.aligned.m16n8k8.row.col.f32.tf32.tf32.f32 "
        "{%0,%1,%2,%3}, {%4,%5,%6,%7}, {%8,%9}, {%0,%1,%2,%3};"
        : "+f"(c[0]), "+f"(c[1]), "+f"(c[2]), "+f"(c[3])
        : "r"(a[0]), "r"(a[1]), "r"(a[2]), "r"(a[3]), "r"(b[0]), "r"(b[1]));
}

__device__ __forceinline__ void cp_async16(void* smem_dst, const void* gmem_src) {
    unsigned s = (unsigned)__cvta_generic_to_shared(smem_dst);
    asm volatile("cp.async.cg.shared.global [%0], [%1], 16;" :: "r"(s), "l"(gmem_src));
}
__device__ __forceinline__ void cp_commit() {
    asm volatile("cp.async.commit_group;");
}
template <int N> __device__ __forceinline__ void cp_wait() {
    asm volatile("cp.async.wait_group %0;" :: "n"(N));
}

// ---------------------------------------------------------------------------
// Prepass: round WEIGHTS only to tf32 (tiny: 4 x 4MB)
// ---------------------------------------------------------------------------
struct RoundArgs {
    const float4* src[4];
    float4*       dst[4];
};

__global__ __launch_bounds__(256) void round_tf32_kernel(RoundArgs a)
{
    int z = blockIdx.z;
    const float4* s = a.src[z];
    float4*       d = a.dst[z];
    int n4 = DD * DD / 4;
    int stride = gridDim.x * blockDim.x;
    for (int i = blockIdx.x * blockDim.x + threadIdx.x; i < n4; i += stride) {
        float4 v = s[i];
        v.x = f2tf32f(v.x); v.y = f2tf32f(v.y);
        v.z = f2tf32f(v.z); v.w = f2tf32f(v.w);
        d[i] = v;
    }
}

// ---------------------------------------------------------------------------
// Pipelined NT GEMM, BM=256 BN=128 BK=16, 512 threads (16 warps 4x4),
// warp tile 64x32 (4x4 m16n8k8). 3-stage cp.async.
// CVT_A: 1 -> A is raw fp32 (cvt at fragment load); 0 -> A pre-rounded.
// B (weights) always pre-rounded.
// ---------------------------------------------------------------------------
#define RS 20
#define STG 3
#define KT (DD / 16)

struct GemmArgs {
    const float* A[3];
    const float* W[3];
    const float* bias[3];
    float* C;
    int out_mode[3];   // 0 plain fp32; 1/2/3 scatter tf32 to g_Q/g_K/g_V
};

template<int CVT_A>
__global__ __launch_bounds__(512, 1) void gemm_pipe_kernel(GemmArgs args)
{
    __shared__ float As[STG][256 * RS];   // 61.4 KB
    __shared__ float Bs[STG][128 * RS];   // 30.7 KB

    int z = blockIdx.z;
    const float* __restrict__ Ain  = args.A[z];
    const float* __restrict__ W    = args.W[z];
    const float* __restrict__ bias = args.bias[z];
    int out_mode = args.out_mode[z];

    int tid  = threadIdx.x;
    int lane = tid & 31;
    int w    = tid >> 5;
    int wm   = w >> 2;          // 0..3 (64 rows each)
    int wn   = w & 3;           // 0..3 (32 cols each)
    int g    = lane >> 2;
    int t    = lane & 3;

    int bm = blockIdx.y * 256;
    int bn = blockIdx.x * 128;

    int ra = tid >> 1;           // 0..255
    int ca = (tid & 1) * 8;      // 0 or 8
    int rb = tid >> 2;           // 0..127
    int cb = (tid & 3) * 4;      // 0,4,8,12

    float c[4][4][4];
#pragma unroll
    for (int mi = 0; mi < 4; mi++)
#pragma unroll
        for (int nj = 0; nj < 4; nj++)
#pragma unroll
            for (int e = 0; e < 4; e++) c[mi][nj][e] = 0.0f;

#pragma unroll
    for (int pf = 0; pf < STG - 1; pf++) {
        int k0 = pf * 16;
        cp_async16(&As[pf][ra * RS + ca],     &Ain[(size_t)(bm + ra) * DD + k0 + ca]);
        cp_async16(&As[pf][ra * RS + ca + 4], &Ain[(size_t)(bm + ra) * DD + k0 + ca + 4]);
        cp_async16(&Bs[pf][rb * RS + cb],     &W[(size_t)(bn + rb) * DD + k0 + cb]);
        cp_commit();
    }
    cp_wait<STG - 2>();
    __syncthreads();

    for (int kt = 0; kt < KT; kt++) {
        int st = kt % STG;

        if (kt + STG - 1 < KT) {
            int ps = (kt + STG - 1) % STG;
            int k0 = (kt + STG - 1) * 16;
            cp_async16(&As[ps][ra * RS + ca],     &Ain[(size_t)(bm + ra) * DD + k0 + ca]);
            cp_async16(&As[ps][ra * RS + ca + 4], &Ain[(size_t)(bm + ra) * DD + k0 + ca + 4]);
            cp_async16(&Bs[ps][rb * RS + cb],     &W[(size_t)(bn + rb) * DD + k0 + cb]);
        }
        cp_commit();

        const float* a_s = As[st];
        const float* b_s = Bs[st];
#pragma unroll
        for (int ks = 0; ks < 2; ks++) {
            unsigned af[4][4], bf[4][2];
#pragma unroll
            for (int mi = 0; mi < 4; mi++) {
                int m = wm * 64 + mi * 16 + g;
                if (CVT_A) {
                    af[mi][0] = f2tf32(a_s[m * RS + ks * 8 + t]);
                    af[mi][1] = f2tf32(a_s[(m + 8) * RS + ks * 8 + t]);
                    af[mi][2] = f2tf32(a_s[m * RS + ks * 8 + t + 4]);
                    af[mi][3] = f2tf32(a_s[(m + 8) * RS + ks * 8 + t + 4]);
                } else {
                    af[mi][0] = __float_as_uint(a_s[m * RS + ks * 8 + t]);
                    af[mi][1] = __float_as_uint(a_s[(m + 8) * RS + ks * 8 + t]);
                    af[mi][2] = __float_as_uint(a_s[m * RS + ks * 8 + t + 4]);
                    af[mi][3] = __float_as_uint(a_s[(m + 8) * RS + ks * 8 + t + 4]);
                }
            }
#pragma unroll
            for (int nj = 0; nj < 4; nj++) {
                int n = wn * 32 + nj * 8 + g;
                bf[nj][0] = __float_as_uint(b_s[n * RS + ks * 8 + t]);
                bf[nj][1] = __float_as_uint(b_s[n * RS + ks * 8 + t + 4]);
            }
#pragma unroll
            for (int mi = 0; mi < 4; mi++)
#pragma unroll
                for (int nj = 0; nj < 4; nj++)
                    mma_tf32(c[mi][nj], af[mi], bf[nj]);
        }

        cp_wait<STG - 2>();
        __syncthreads();
    }

#pragma unroll
    for (int mi = 0; mi < 4; mi++) {
#pragma unroll
        for (int nj = 0; nj < 4; nj++) {
            int m = bm + wm * 64 + mi * 16 + g;
            int n = bn + wn * 32 + nj * 8 + 2 * t;
            float b0 = bias[n], b1 = bias[n + 1];
            if (out_mode == 0) {
                *(float2*)&args.C[(size_t)m * DD + n] =
                    make_float2(c[mi][nj][0] + b0, c[mi][nj][1] + b1);
                *(float2*)&args.C[(size_t)(m + 8) * DD + n] =
                    make_float2(c[mi][nj][2] + b0, c[mi][nj][3] + b1);
            } else {
                float2 v0 = make_float2(f2tf32f(c[mi][nj][0] + b0), f2tf32f(c[mi][nj][1] + b1));
                float2 v1 = make_float2(f2tf32f(c[mi][nj][2] + b0), f2tf32f(c[mi][nj][3] + b1));
                int b  = m >> 11;
                int s  = m & (SS - 1);
                int h  = n >> 6;
                int dk = n & (DKK - 1);
                float* dst = (out_mode == 1) ? g_Q : (out_mode == 2) ? g_K : g_V;
                size_t base = (((size_t)(b * HH + h)) * SS) * DKK + dk;
                *(float2*)&dst[base + (size_t)s * DKK]  = v0;
                int s1 = (m + 8) & (SS - 1);
                *(float2*)&dst[base + (size_t)s1 * DKK] = v1;
            }
        }
    }
}

// ---------------------------------------------------------------------------
// Causal flash attention, tf32 MMA. BQ=128, 256 threads (8 warps), warp owns
// 16 Q rows. K/V 64-key tiles, double-buffered cp.async. Q/K/V pre-rounded.
// ---------------------------------------------------------------------------
#define SCALE_LOG2E 0.1803368801111244f

__global__ __launch_bounds__(256, 2) void attn_tc_kernel()
{
    __shared__ unsigned QPs[128][68];     // Q tile then P   (34.8 KB)
    __shared__ float    Ks[2][64][68];    // 34.8 KB
    __shared__ float    Vs[2][64][72];    // 36.9 KB

    int tid  = threadIdx.x;
    int lane = tid & 31;
    int w    = tid >> 5;       // 0..7
    int g    = lane >> 2;
    int t    = lane & 3;
    int wrow = w * 16;

    int qb = gridDim.x - 1 - blockIdx.x;  // heavy blocks first
    int bh = blockIdx.y;
    int b  = bh >> 4;
    int h  = bh & (HH - 1);
    size_t head = (size_t)bh * SS * DKK;

    // stage Q tile [128][64] (raw bits)
#pragma unroll
    for (int it = 0; it < 8; it++) {
        int i  = it * 256 + tid;
        int r  = i >> 4;
        int c4 = (i & 15) << 2;
        float4 v4 = *(const float4*)&g_Q[head + (size_t)(qb * 128 + r) * DKK + c4];
        QPs[r][c4 + 0] = __float_as_uint(v4.x);
        QPs[r][c4 + 1] = __float_as_uint(v4.y);
        QPs[r][c4 + 2] = __float_as_uint(v4.z);
        QPs[r][c4 + 3] = __float_as_uint(v4.w);
    }

    // prefetch K/V tile 0
#pragma unroll
    for (int it = 0; it < 4; it++) {
        int ch = it * 256 + tid;
        int r  = ch >> 4;
        int c4 = (ch & 15) << 2;
        size_t gi = head + (size_t)r * DKK + c4;
        cp_async16(&Ks[0][r][c4], &g_K[gi]);
        cp_async16(&Vs[0][r][c4], &g_V[gi]);
    }
    cp_commit();
    __syncthreads();

    // Q fragments
    unsigned qf[8][4];
#pragma unroll
    for (int ks = 0; ks < 8; ks++) {
        qf[ks][0] = QPs[wrow + g][ks * 8 + t];
        qf[ks][1] = QPs[wrow + g + 8][ks * 8 + t];
        qf[ks][2] = QPs[wrow + g][ks * 8 + t + 4];
        qf[ks][3] = QPs[wrow + g + 8][ks * 8 + t + 4];
    }

    float o[8][4];
#pragma unroll
    for (int nj = 0; nj < 8; nj++)
#pragma unroll
        for (int e = 0; e < 4; e++) o[nj][e] = 0.0f;
    float m0 = -1e30f, m1 = -1e30f, l0 = 0.0f, l1 = 0.0f;

    int jmax = 2 * qb + 1;
    for (int j = 0; j <= jmax; j++) {
        int cur = j & 1;
        __syncthreads();

        if (j < jmax) {
            int nxt = (j + 1) & 1;
#pragma unroll
            for (int it = 0; it < 4; it++) {
                int ch = it * 256 + tid;
                int r  = ch >> 4;
                int c4 = (ch & 15) << 2;
                size_t gi = head + (size_t)((j + 1) * 64 + r) * DKK + c4;
                cp_async16(&Ks[nxt][r][c4], &g_K[gi]);
                cp_async16(&Vs[nxt][r][c4], &g_V[gi]);
            }
        }
        cp_commit();
        cp_wait<1>();
        __syncthreads();

        // warps whose rows are all masked for this tile skip compute
        bool active = (64 * j <= 128 * qb + wrow + 15);
        if (active) {
            float s[8][4];
#pragma unroll
            for (int nj = 0; nj < 8; nj++)
#pragma unroll
                for (int e = 0; e < 4; e++) s[nj][e] = 0.0f;

#pragma unroll
            for (int ks = 0; ks < 8; ks++) {
#pragma unroll
                for (int nj = 0; nj < 8; nj++) {
                    unsigned bf[2];
                    bf[0] = __float_as_uint(Ks[cur][nj * 8 + g][ks * 8 + t]);
                    bf[1] = __float_as_uint(Ks[cur][nj * 8 + g][ks * 8 + t + 4]);
                    mma_tf32(s[nj], qf[ks], bf);
                }
            }

#pragma unroll
            for (int nj = 0; nj < 8; nj++)
#pragma unroll
                for (int e = 0; e < 4; e++) s[nj][e] *= SCALE_LOG2E;

            if (j >= 2 * qb) {  // tiles overlapping the diagonal
                int qi0 = 128 * qb + wrow + g;
                int qi1 = qi0 + 8;
#pragma unroll
                for (int nj = 0; nj < 8; nj++) {
                    int c0 = 64 * j + nj * 8 + 2 * t;
                    if (c0     > qi0) s[nj][0] = -1e30f;
                    if (c0 + 1 > qi0) s[nj][1] = -1e30f;
                    if (c0     > qi1) s[nj][2] = -1e30f;
                    if (c0 + 1 > qi1) s[nj][3] = -1e30f;
                }
            }

            float mx0 = -1e30f, mx1 = -1e30f;
#pragma unroll
            for (int nj = 0; nj < 8; nj++) {
                mx0 = fmaxf(mx0, fmaxf(s[nj][0], s[nj][1]));
                mx1 = fmaxf(mx1, fmaxf(s[nj][2], s[nj][3]));
            }
            mx0 = fmaxf(mx0, __shfl_xor_sync(0xffffffffu, mx0, 1));
            mx0 = fmaxf(mx0, __shfl_xor_sync(0xffffffffu, mx0, 2));
            mx1 = fmaxf(mx1, __shfl_xor_sync(0xffffffffu, mx1, 1));
            mx1 = fmaxf(mx1, __shfl_xor_sync(0xffffffffu, mx1, 2));

            float m0n = fmaxf(m0, mx0), m1n = fmaxf(m1, mx1);
            float a0 = ex2(m0 - m0n),   a1 = ex2(m1 - m1n);
            m0 = m0n; m1 = m1n;

            float rs0 = 0.0f, rs1 = 0.0f;
#pragma unroll
            for (int nj = 0; nj < 8; nj++) {
                float p;
                p = ex2(s[nj][0] - m0n); rs0 += p; s[nj][0] = p;
                p = ex2(s[nj][1] - m0n); rs0 += p; s[nj][1] = p;
                p = ex2(s[nj][2] - m1n); rs1 += p; s[nj][2] = p;
                p = ex2(s[nj][3] - m1n); rs1 += p; s[nj][3] = p;
            }
            rs0 += __shfl_xor_sync(0xffffffffu, rs0, 1);
            rs0 += __shfl_xor_sync(0xffffffffu, rs0, 2);
            rs1 += __shfl_xor_sync(0xffffffffu, rs1, 1);
            rs1 += __shfl_xor_sync(0xffffffffu, rs1, 2);

            l0 = l0 * a0 + rs0;
            l1 = l1 * a1 + rs1;
#pragma unroll
            for (int nj = 0; nj < 8; nj++) {
                o[nj][0] *= a0; o[nj][1] *= a0;
                o[nj][2] *= a1; o[nj][3] *= a1;
            }

            // P -> smem (warp-private rows)
#pragma unroll
            for (int nj = 0; nj < 8; nj++) {
                int cc = nj * 8 + 2 * t;
                QPs[wrow + g][cc]         = f2tf32(s[nj][0]);
                QPs[wrow + g][cc + 1]     = f2tf32(s[nj][1]);
                QPs[wrow + g + 8][cc]     = f2tf32(s[nj][2]);
                QPs[wrow + g + 8][cc + 1] = f2tf32(s[nj][3]);
            }
            __syncwarp();

            // O += P @ V
#pragma unroll
            for (int ks = 0; ks < 8; ks++) {
                unsigned pf[4];
                pf[0] = QPs[wrow + g][ks * 8 + t];
                pf[1] = QPs[wrow + g + 8][ks * 8 + t];
                pf[2] = QPs[wrow + g][ks * 8 + t + 4];
                pf[3] = QPs[wrow + g + 8][ks * 8 + t + 4];
#pragma unroll
                for (int nj = 0; nj < 8; nj++) {
                    unsigned vf[2];
                    vf[0] = __float_as_uint(Vs[cur][ks * 8 + t][nj * 8 + g]);
                    vf[1] = __float_as_uint(Vs[cur][ks * 8 + t + 4][nj * 8 + g]);
                    mma_tf32(o[nj], pf, vf);
                }
            }
        }
    }

    // epilogue: normalize + tf32-round (out-proj consumes raw bits)
    float inv0 = 1.0f / l0, inv1 = 1.0f / l1;
    int row0 = qb * 128 + wrow + g;
    size_t base0 = ((size_t)(b * SS + row0)) * DD + h * 64;
    size_t base1 = base0 + (size_t)8 * DD;
#pragma unroll
    for (int nj = 0; nj < 8; nj++) {
        int cc = nj * 8 + 2 * t;
        *(float2*)&g_Ctx[base0 + cc] =
            make_float2(f2tf32f(o[nj][0] * inv0), f2tf32f(o[nj][1] * inv0));
        *(float2*)&g_Ctx[base1 + cc] =
            make_float2(f2tf32f(o[nj][2] * inv1), f2tf32f(o[nj][3] * inv1));
    }
}

// ---------------------------------------------------------------------------
// kernel_launch
// ---------------------------------------------------------------------------
extern "C" void kernel_launch(void* const* d_in, const int* in_sizes, int n_in,
                              void* d_out, int out_size)
{
    const float* q    = (const float*)d_in[0];
    const float* k    = (const float*)d_in[1];
    const float* v    = (const float*)d_in[2];
    const float* wq_w = (const float*)d_in[4];
    const float* wq_b = (const float*)d_in[5];
    const float* wk_w = (const float*)d_in[6];
    const float* wk_b = (const float*)d_in[7];
    const float* wv_w = (const float*)d_in[8];
    const float* wv_b = (const float*)d_in[9];
    const float* wo_w = (const float*)d_in[10];
    const float* wo_b = (const float*)d_in[11];
    float* out = (float*)d_out;

    void *p_w, *p_ctx;
    cudaGetSymbolAddress(&p_w,  g_w);
    cudaGetSymbolAddress(&p_ctx, g_Ctx);
    float* w0 = (float*)p_w;
    float* w1 = w0 + DD * DD;
    float* w2 = w0 + 2 * DD * DD;
    float* w3 = w0 + 3 * DD * DD;

    // prepass: round weights to tf32 (8 MB r+w, ~3us)
    RoundArgs ra;
    ra.src[0] = (const float4*)wq_w; ra.dst[0] = (float4*)w0;
    ra.src[1] = (const float4*)wk_w; ra.dst[1] = (float4*)w1;
    ra.src[2] = (const float4*)wv_w; ra.dst[2] = (float4*)w2;
    ra.src[3] = (const float4*)wo_w; ra.dst[3] = (float4*)w3;
    round_tf32_kernel<<<dim3(64, 1, 4), 256>>>(ra);

    // fused QKV projections (A raw -> cvt in loop)
    GemmArgs qkv;
    qkv.A[0] = q;    qkv.A[1] = k;    qkv.A[2] = v;
    qkv.W[0] = w0;   qkv.W[1] = w1;   qkv.W[2] = w2;
    qkv.bias[0] = wq_b; qkv.bias[1] = wk_b; qkv.bias[2] = wv_b;
    qkv.C = nullptr;
    qkv.out_mode[0] = 1; qkv.out_mode[1] = 2; qkv.out_mode[2] = 3;
    gemm_pipe_kernel<1><<<dim3(DD / 128, MM / 256, 3), 512>>>(qkv);

    // attention
    attn_tc_kernel<<<dim3(SS / 128, BB * HH), 256>>>();

    // output projection (A = g_Ctx pre-rounded -> no cvt)
    GemmArgs og;
    og.A[0] = (const float*)p_ctx; og.A[1] = og.A[0]; og.A[2] = og.A[0];
    og.W[0] = w3; og.W[1] = w3; og.W[2] = w3;
    og.bias[0] = wo_b; og.bias[1] = wo_b; og.bias[2] = wo_b;
    og.C = out;
    og.out_mode[0] = 0; og.out_mode[1] = 0; og.out_mode[2] = 0;
    gemm_pipe_kernel<0><<<dim3(DD / 128, MM / 256, 1), 512>>>(og);
}

// round 7
// speedup vs baseline: 1.0691x; 1.0691x over previous
#include <cuda_runtime.h>
#include <cuda_bf16.h>
#include <math.h>

// Problem constants
#define BB 2
#define SS 2048
#define DD 1024
#define HH 16
#define DKK 64
#define MM (BB * SS)

// ---------------------------------------------------------------------------
// Scratch (device globals)
// ---------------------------------------------------------------------------
__device__ float g_Q[BB * HH * SS * DKK];   // [B,H,S,DK]  tf32-rounded
__device__ float g_K[BB * HH * SS * DKK];
__device__ float g_V[BB * HH * SS * DKK];
__device__ float g_Ctx[BB * SS * DD];       // [B,S,D]     tf32-rounded
__device__ float g_w[4][DD * DD];           // tf32-rounded weights q,k,v,o

// ---------------------------------------------------------------------------
// helpers
// ---------------------------------------------------------------------------
__device__ __forceinline__ unsigned f2tf32(float x) {
    unsigned y;
    asm("cvt.rna.tf32.f32 %0, %1;" : "=r"(y) : "f"(x));
    return y;
}
__device__ __forceinline__ float f2tf32f(float x) { return __uint_as_float(f2tf32(x)); }

__device__ __forceinline__ float ex2(float x) {
    float y;
    asm("ex2.approx.f32 %0, %1;" : "=f"(y) : "f"(x));
    return y;
}

__device__ __forceinline__ void mma_tf32(float* c, const unsigned* a, const unsigned* b) {
    asm volatile("mma.sync.aligned.m16n8k8.row.col.f32.tf32.tf32.f32 "
        "{%0,%1,%2,%3}, {%4,%5,%6,%7}, {%8,%9}, {%0,%1,%2,%3};"
        : "+f"(c[0]), "+f"(c[1]), "+f"(c[2]), "+f"(c[3])
        : "r"(a[0]), "r"(a[1]), "r"(a[2]), "r"(a[3]), "r"(b[0]), "r"(b[1]));
}

__device__ __forceinline__ unsigned smem_u32(const void* p) {
    return (unsigned)__cvta_generic_to_shared(p);
}
// ldmatrix x4: A-fragment (16x8 b32). r0=(g,t) r1=(g+8,t) r2=(g,t+4) r3=(g+8,t+4)
__device__ __forceinline__ void ldsm_x4(unsigned* r, unsigned addr) {
    asm volatile("ldmatrix.sync.aligned.m8n8.x4.shared.b16 {%0,%1,%2,%3}, [%4];"
        : "=r"(r[0]), "=r"(r[1]), "=r"(r[2]), "=r"(r[3]) : "r"(addr));
}
// ldmatrix x2: B-fragment (8x8 b32 row-major n x k). r0=(g,t) r1=(g,t+4)
__device__ __forceinline__ void ldsm_x2(unsigned* r, unsigned addr) {
    asm volatile("ldmatrix.sync.aligned.m8n8.x2.shared.b16 {%0,%1}, [%2];"
        : "=r"(r[0]), "=r"(r[1]) : "r"(addr));
}

__device__ __forceinline__ void cp_async16(void* smem_dst, const void* gmem_src) {
    unsigned s = (unsigned)__cvta_generic_to_shared(smem_dst);
    asm volatile("cp.async.cg.shared.global [%0], [%1], 16;" :: "r"(s), "l"(gmem_src));
}
__device__ __forceinline__ void cp_commit() {
    asm volatile("cp.async.commit_group;");
}
template <int N> __device__ __forceinline__ void cp_wait() {
    asm volatile("cp.async.wait_group %0;" :: "n"(N));
}

// ---------------------------------------------------------------------------
// Prepass: round WEIGHTS to tf32 (4 x 4MB, ~5us)
// ---------------------------------------------------------------------------
struct RoundArgs {
    const float4* src[4];
    float4*       dst[4];
};

__global__ __launch_bounds__(256) void round_tf32_kernel(RoundArgs a)
{
    int z = blockIdx.z;
    const float4* s = a.src[z];
    float4*       d = a.dst[z];
    int n4 = DD * DD / 4;
    int stride = gridDim.x * blockDim.x;
    for (int i = blockIdx.x * blockDim.x + threadIdx.x; i < n4; i += stride) {
        float4 v = s[i];
        v.x = f2tf32f(v.x); v.y = f2tf32f(v.y);
        v.z = f2tf32f(v.z); v.w = f2tf32f(v.w);
        d[i] = v;
    }
}

// ---------------------------------------------------------------------------
// Pipelined NT GEMM, BM=BN=128, BK=16, 256 threads (8 warps 2x4, 64x32/warp),
// 3-stage cp.async ring, ldmatrix fragment loads.
// CVT_A: 1 -> A raw fp32 (cvt after ldmatrix); 0 -> A pre-rounded.
// W always pre-rounded. out_mode 0 plain; 1/2/3 scatter tf32 to g_Q/g_K/g_V.
// ---------------------------------------------------------------------------
#define RS 20
#define STG 3
#define KT (DD / 16)

struct GemmArgs {
    const float* A[3];
    const float* W[3];
    const float* bias[3];
    float* C;
    int out_mode[3];
};

template<int CVT_A>
__global__ __launch_bounds__(256, 2) void gemm_pipe_kernel(GemmArgs args)
{
    __shared__ float As[STG][128 * RS];
    __shared__ float Bs[STG][128 * RS];

    int z = blockIdx.z;
    const float* __restrict__ Ain  = args.A[z];
    const float* __restrict__ W    = args.W[z];
    const float* __restrict__ bias = args.bias[z];
    int out_mode = args.out_mode[z];

    int tid  = threadIdx.x;
    int lane = tid & 31;
    int w    = tid >> 5;
    int wm   = w >> 2;          // 0..1
    int wn   = w & 3;           // 0..3
    int g    = lane >> 2;
    int t    = lane & 3;

    int bm = blockIdx.y * 128;
    int bn = blockIdx.x * 128;

    int r0c = tid >> 1;
    int c0c = (tid & 1) * 8;

    // ldmatrix per-lane base offsets (in words)
    int aoff = (wm * 64 + (lane & 15)) * RS + (lane >> 4) * 4;
    int boff = (wn * 32 + (lane & 7)) * RS + ((lane >> 3) & 1) * 4;

    unsigned a_smem0 = smem_u32(&As[0][0]);
    unsigned b_smem0 = smem_u32(&Bs[0][0]);

    float c[4][4][4];
#pragma unroll
    for (int mi = 0; mi < 4; mi++)
#pragma unroll
        for (int nj = 0; nj < 4; nj++)
#pragma unroll
            for (int e = 0; e < 4; e++) c[mi][nj][e] = 0.0f;

#pragma unroll
    for (int pf = 0; pf < STG - 1; pf++) {
        int k0 = pf * 16;
        cp_async16(&As[pf][r0c * RS + c0c],     &Ain[(size_t)(bm + r0c) * DD + k0 + c0c]);
        cp_async16(&As[pf][r0c * RS + c0c + 4], &Ain[(size_t)(bm + r0c) * DD + k0 + c0c + 4]);
        cp_async16(&Bs[pf][r0c * RS + c0c],     &W[(size_t)(bn + r0c) * DD + k0 + c0c]);
        cp_async16(&Bs[pf][r0c * RS + c0c + 4], &W[(size_t)(bn + r0c) * DD + k0 + c0c + 4]);
        cp_commit();
    }
    cp_wait<STG - 2>();
    __syncthreads();

    for (int kt = 0; kt < KT; kt++) {
        int st = kt % STG;

        if (kt + STG - 1 < KT) {
            int ps = (kt + STG - 1) % STG;
            int k0 = (kt + STG - 1) * 16;
            cp_async16(&As[ps][r0c * RS + c0c],     &Ain[(size_t)(bm + r0c) * DD + k0 + c0c]);
            cp_async16(&As[ps][r0c * RS + c0c + 4], &Ain[(size_t)(bm + r0c) * DD + k0 + c0c + 4]);
            cp_async16(&Bs[ps][r0c * RS + c0c],     &W[(size_t)(bn + r0c) * DD + k0 + c0c]);
            cp_async16(&Bs[ps][r0c * RS + c0c + 4], &W[(size_t)(bn + r0c) * DD + k0 + c0c + 4]);
        }
        cp_commit();

        unsigned a_base = a_smem0 + (unsigned)(st * 128 * RS) * 4u;
        unsigned b_base = b_smem0 + (unsigned)(st * 128 * RS) * 4u;

#pragma unroll
        for (int ks = 0; ks < 2; ks++) {
            unsigned af[4][4], bf[4][2];
#pragma unroll
            for (int mi = 0; mi < 4; mi++) {
                unsigned addr = a_base + (unsigned)(aoff + mi * 16 * RS + ks * 8) * 4u;
                ldsm_x4(af[mi], addr);
                if (CVT_A) {
#pragma unroll
                    for (int e = 0; e < 4; e++)
                        af[mi][e] = f2tf32(__uint_as_float(af[mi][e]));
                }
            }
#pragma unroll
            for (int nj = 0; nj < 4; nj++) {
                unsigned addr = b_base + (unsigned)(boff + nj * 8 * RS + ks * 8) * 4u;
                ldsm_x2(bf[nj], addr);
            }
#pragma unroll
            for (int mi = 0; mi < 4; mi++)
#pragma unroll
                for (int nj = 0; nj < 4; nj++)
                    mma_tf32(c[mi][nj], af[mi], bf[nj]);
        }

        cp_wait<STG - 2>();
        __syncthreads();
    }

#pragma unroll
    for (int mi = 0; mi < 4; mi++) {
#pragma unroll
        for (int nj = 0; nj < 4; nj++) {
            int m = bm + wm * 64 + mi * 16 + g;
            int n = bn + wn * 32 + nj * 8 + 2 * t;
            float b0 = bias[n], b1 = bias[n + 1];
            if (out_mode == 0) {
                *(float2*)&args.C[(size_t)m * DD + n] =
                    make_float2(c[mi][nj][0] + b0, c[mi][nj][1] + b1);
                *(float2*)&args.C[(size_t)(m + 8) * DD + n] =
                    make_float2(c[mi][nj][2] + b0, c[mi][nj][3] + b1);
            } else {
                float2 v0 = make_float2(f2tf32f(c[mi][nj][0] + b0), f2tf32f(c[mi][nj][1] + b1));
                float2 v1 = make_float2(f2tf32f(c[mi][nj][2] + b0), f2tf32f(c[mi][nj][3] + b1));
                int b  = m >> 11;
                int s  = m & (SS - 1);
                int h  = n >> 6;
                int dk = n & (DKK - 1);
                float* dst = (out_mode == 1) ? g_Q : (out_mode == 2) ? g_K : g_V;
                size_t base = (((size_t)(b * HH + h)) * SS) * DKK + dk;
                *(float2*)&dst[base + (size_t)s * DKK]  = v0;
                int s1 = (m + 8) & (SS - 1);
                *(float2*)&dst[base + (size_t)s1 * DKK] = v1;
            }
        }
    }
}

// ---------------------------------------------------------------------------
// Causal flash attention, tf32 MMA, ldmatrix K/P fragment loads.
// grid = (S/64, B*H), 128 threads (4 warps), warp owns 16 Q rows.
// Q/K/V pre-rounded tf32 -> raw-bit staging (float4).
// ---------------------------------------------------------------------------
#define SCALE_LOG2E 0.1803368801111244f

__global__ __launch_bounds__(128) void attn_tc_kernel()
{
    __shared__ float QPs[64][68];     // Q tile then P (tf32 bits as float)
    __shared__ float Ks[64][68];
    __shared__ float Vs[64][72];

    int tid  = threadIdx.x;
    int lane = tid & 31;
    int w    = tid >> 5;
    int g    = lane >> 2;
    int t    = lane & 3;
    int wrow = w * 16;

    int qb = gridDim.x - 1 - blockIdx.x;   // heavy blocks first
    int bh = blockIdx.y;
    int b  = bh >> 4;
    int h  = bh & (HH - 1);
    size_t head = (size_t)bh * SS * DKK;

    // ldmatrix per-lane base offsets (words)
    int qpoff = (wrow + (lane & 15)) * 68 + (lane >> 4) * 4;   // x4 (Q/P frags)
    int koff  = (lane & 7) * 68 + ((lane >> 3) & 1) * 4;       // x2 (K frags)
    unsigned qp_base = smem_u32(&QPs[0][0]);
    unsigned k_base  = smem_u32(&Ks[0][0]);

    // ---- stage Q tile [64][64] (raw bits, float4) ----
#pragma unroll
    for (int it = 0; it < 8; it++) {
        int i  = it * 128 + tid;
        int r  = i >> 4;
        int c4 = (i & 15) << 2;
        *(float4*)&QPs[r][c4] =
            *(const float4*)&g_Q[head + (size_t)(qb * 64 + r) * DKK + c4];
    }
    __syncthreads();

    // ---- Q fragments to registers (8 k-steps, ldmatrix x4) ----
    unsigned qf[8][4];
#pragma unroll
    for (int ks = 0; ks < 8; ks++)
        ldsm_x4(qf[ks], qp_base + (unsigned)(qpoff + ks * 8) * 4u);

    float o[8][4];
#pragma unroll
    for (int nj = 0; nj < 8; nj++)
#pragma unroll
        for (int e = 0; e < 4; e++) o[nj][e] = 0.0f;
    float m0 = -1e30f, m1 = -1e30f, l0 = 0.0f, l1 = 0.0f;

    for (int j = 0; j <= qb; j++) {
        __syncthreads();
        // ---- stage K,V tiles [64][64] (raw bits, float4) ----
#pragma unroll
        for (int it = 0; it < 8; it++) {
            int i  = it * 128 + tid;
            int r  = i >> 4;
            int c4 = (i & 15) << 2;
            size_t gi = head + (size_t)(j * 64 + r) * DKK + c4;
            *(float4*)&Ks[r][c4] = *(const float4*)&g_K[gi];
            *(float4*)&Vs[r][c4] = *(const float4*)&g_V[gi];
        }
        __syncthreads();

        // ---- S = Q @ K^T (K frags via ldmatrix x2) ----
        float s[8][4];
#pragma unroll
        for (int nj = 0; nj < 8; nj++)
#pragma unroll
            for (int e = 0; e < 4; e++) s[nj][e] = 0.0f;

#pragma unroll
        for (int ks = 0; ks < 8; ks++) {
#pragma unroll
            for (int nj = 0; nj < 8; nj++) {
                unsigned bf[2];
                ldsm_x2(bf, k_base + (unsigned)(koff + nj * 8 * 68 + ks * 8) * 4u);
                mma_tf32(s[nj], qf[ks], bf);
            }
        }

#pragma unroll
        for (int nj = 0; nj < 8; nj++)
#pragma unroll
            for (int e = 0; e < 4; e++) s[nj][e] *= SCALE_LOG2E;

        if (j == qb) {  // diagonal tile causal mask (local coords)
#pragma unroll
            for (int nj = 0; nj < 8; nj++) {
                int c0 = nj * 8 + 2 * t;
                if (c0     > wrow + g)     s[nj][0] = -1e30f;
                if (c0 + 1 > wrow + g)     s[nj][1] = -1e30f;
                if (c0     > wrow + g + 8) s[nj][2] = -1e30f;
                if (c0 + 1 > wrow + g + 8) s[nj][3] = -1e30f;
            }
        }

        float mx0 = -1e30f, mx1 = -1e30f;
#pragma unroll
        for (int nj = 0; nj < 8; nj++) {
            mx0 = fmaxf(mx0, fmaxf(s[nj][0], s[nj][1]));
            mx1 = fmaxf(mx1, fmaxf(s[nj][2], s[nj][3]));
        }
        mx0 = fmaxf(mx0, __shfl_xor_sync(0xffffffffu, mx0, 1));
        mx0 = fmaxf(mx0, __shfl_xor_sync(0xffffffffu, mx0, 2));
        mx1 = fmaxf(mx1, __shfl_xor_sync(0xffffffffu, mx1, 1));
        mx1 = fmaxf(mx1, __shfl_xor_sync(0xffffffffu, mx1, 2));

        float m0n = fmaxf(m0, mx0), m1n = fmaxf(m1, mx1);
        float a0 = ex2(m0 - m0n),   a1 = ex2(m1 - m1n);
        m0 = m0n; m1 = m1n;

        float rs0 = 0.0f, rs1 = 0.0f;
#pragma unroll
        for (int nj = 0; nj < 8; nj++) {
            float p;
            p = ex2(s[nj][0] - m0n); rs0 += p; s[nj][0] = p;
            p = ex2(s[nj][1] - m0n); rs0 += p; s[nj][1] = p;
            p = ex2(s[nj][2] - m1n); rs1 += p; s[nj][2] = p;
            p = ex2(s[nj][3] - m1n); rs1 += p; s[nj][3] = p;
        }
        rs0 += __shfl_xor_sync(0xffffffffu, rs0, 1);
        rs0 += __shfl_xor_sync(0xffffffffu, rs0, 2);
        rs1 += __shfl_xor_sync(0xffffffffu, rs1, 1);
        rs1 += __shfl_xor_sync(0xffffffffu, rs1, 2);

        l0 = l0 * a0 + rs0;
        l1 = l1 * a1 + rs1;
#pragma unroll
        for (int nj = 0; nj < 8; nj++) {
            o[nj][0] *= a0; o[nj][1] *= a0;
            o[nj][2] *= a1; o[nj][3] *= a1;
        }

        // ---- P -> smem (warp-private rows, float2 stores of tf32 bits) ----
#pragma unroll
        for (int nj = 0; nj < 8; nj++) {
            int cc = nj * 8 + 2 * t;
            *(float2*)&QPs[wrow + g][cc] =
                make_float2(f2tf32f(s[nj][0]), f2tf32f(s[nj][1]));
            *(float2*)&QPs[wrow + g + 8][cc] =
                make_float2(f2tf32f(s[nj][2]), f2tf32f(s[nj][3]));
        }
        __syncwarp();

        // ---- O += P @ V (P frags via ldmatrix x4; V scalar LDS) ----
#pragma unroll
        for (int ks = 0; ks < 8; ks++) {
            unsigned pf[4];
            ldsm_x4(pf, qp_base + (unsigned)(qpoff + ks * 8) * 4u);
#pragma unroll
            for (int nj = 0; nj < 8; nj++) {
                unsigned vf[2];
                vf[0] = __float_as_uint(Vs[ks * 8 + t][nj * 8 + g]);
                vf[1] = __float_as_uint(Vs[ks * 8 + t + 4][nj * 8 + g]);
                mma_tf32(o[nj], pf, vf);
            }
        }
    }

    // ---- epilogue: normalize + tf32-round (out-proj consumes raw bits) ----
    float inv0 = 1.0f / l0, inv1 = 1.0f / l1;
    int row0 = qb * 64 + wrow + g;
    size_t base0 = ((size_t)(b * SS + row0)) * DD + h * 64;
    size_t base1 = base0 + (size_t)8 * DD;
#pragma unroll
    for (int nj = 0; nj < 8; nj++) {
        int cc = nj * 8 + 2 * t;
        *(float2*)&g_Ctx[base0 + cc] =
            make_float2(f2tf32f(o[nj][0] * inv0), f2tf32f(o[nj][1] * inv0));
        *(float2*)&g_Ctx[base1 + cc] =
            make_float2(f2tf32f(o[nj][2] * inv1), f2tf32f(o[nj][3] * inv1));
    }
}

// ---------------------------------------------------------------------------
// kernel_launch
// ---------------------------------------------------------------------------
extern "C" void kernel_launch(void* const* d_in, const int* in_sizes, int n_in,
                              void* d_out, int out_size)
{
    const float* q    = (const float*)d_in[0];
    const float* k    = (const float*)d_in[1];
    const float* v    = (const float*)d_in[2];
    const float* wq_w = (const float*)d_in[4];
    const float* wq_b = (const float*)d_in[5];
    const float* wk_w = (const float*)d_in[6];
    const float* wk_b = (const float*)d_in[7];
    const float* wv_w = (const float*)d_in[8];
    const float* wv_b = (const float*)d_in[9];
    const float* wo_w = (const float*)d_in[10];
    const float* wo_b = (const float*)d_in[11];
    float* out = (float*)d_out;

    void *p_w, *p_ctx;
    cudaGetSymbolAddress(&p_w,  g_w);
    cudaGetSymbolAddress(&p_ctx, g_Ctx);
    float* w0 = (float*)p_w;
    float* w1 = w0 + DD * DD;
    float* w2 = w0 + 2 * DD * DD;
    float* w3 = w0 + 3 * DD * DD;

    // prepass: round weights to tf32
    RoundArgs ra;
    ra.src[0] = (const float4*)wq_w; ra.dst[0] = (float4*)w0;
    ra.src[1] = (const float4*)wk_w; ra.dst[1] = (float4*)w1;
    ra.src[2] = (const float4*)wv_w; ra.dst[2] = (float4*)w2;
    ra.src[3] = (const float4*)wo_w; ra.dst[3] = (float4*)w3;
    round_tf32_kernel<<<dim3(64, 1, 4), 256>>>(ra);

    // fused QKV projections (A raw -> cvt after ldmatrix)
    GemmArgs qkv;
    qkv.A[0] = q;    qkv.A[1] = k;    qkv.A[2] = v;
    qkv.W[0] = w0;   qkv.W[1] = w1;   qkv.W[2] = w2;
    qkv.bias[0] = wq_b; qkv.bias[1] = wk_b; qkv.bias[2] = wv_b;
    qkv.C = nullptr;
    qkv.out_mode[0] = 1; qkv.out_mode[1] = 2; qkv.out_mode[2] = 3;
    gemm_pipe_kernel<1><<<dim3(DD / 128, MM / 128, 3), 256>>>(qkv);

    // attention
    attn_tc_kernel<<<dim3(SS / 64, BB * HH), 128>>>();

    // output projection (A = g_Ctx pre-rounded -> no cvt)
    GemmArgs og;
    og.A[0] = (const float*)p_ctx; og.A[1] = og.A[0]; og.A[2] = og.A[0];
    og.W[0] = w3; og.W[1] = w3; og.W[2] = w3;
    og.bias[0] = wo_b; og.bias[1] = wo_b; og.bias[2] = wo_b;
    og.C = out;
    og.out_mode[0] = 0; og.out_mode[1] = 0; og.out_mode[2] = 0;
    gemm_pipe_kernel<0><<<dim3(DD / 128, MM / 128, 1), 256>>>(og);
}

// round 9
// speedup vs baseline: 1.1541x; 1.0795x over previous
#include <cuda_runtime.h>
#include <cuda_bf16.h>
#include <math.h>

// Problem constants
#define BB 2
#define SS 2048
#define DD 1024
#define HH 16
#define DKK 64
#define MM (BB * SS)

// ---------------------------------------------------------------------------
// Scratch (device globals)
// ---------------------------------------------------------------------------
__device__ float g_Q[BB * HH * SS * DKK];   // [B,H,S,DK]  tf32-rounded
__device__ float g_K[BB * HH * SS * DKK];
__device__ float g_V[BB * HH * SS * DKK];
__device__ float g_Ctx[BB * SS * DD];       // [B,S,D]     tf32-rounded

// ---------------------------------------------------------------------------
// helpers
// ---------------------------------------------------------------------------
__device__ __forceinline__ unsigned f2tf32(float x) {
    unsigned y;
    asm("cvt.rna.tf32.f32 %0, %1;" : "=r"(y) : "f"(x));
    return y;
}
__device__ __forceinline__ float f2tf32f(float x) { return __uint_as_float(f2tf32(x)); }

__device__ __forceinline__ float ex2(float x) {
    float y;
    asm("ex2.approx.f32 %0, %1;" : "=f"(y) : "f"(x));
    return y;
}

__device__ __forceinline__ void mma_tf32(float* c, const unsigned* a, const unsigned* b) {
    asm volatile("mma.sync.aligned.m16n8k8.row.col.f32.tf32.tf32.f32 "
        "{%0,%1,%2,%3}, {%4,%5,%6,%7}, {%8,%9}, {%0,%1,%2,%3};"
        : "+f"(c[0]), "+f"(c[1]), "+f"(c[2]), "+f"(c[3])
        : "r"(a[0]), "r"(a[1]), "r"(a[2]), "r"(a[3]), "r"(b[0]), "r"(b[1]));
}

__device__ __forceinline__ void cp_async16(void* smem_dst, const void* gmem_src) {
    unsigned s = (unsigned)__cvta_generic_to_shared(smem_dst);
    asm volatile("cp.async.cg.shared.global [%0], [%1], 16;" :: "r"(s), "l"(gmem_src));
}
__device__ __forceinline__ void cp_commit() {
    asm volatile("cp.async.commit_group;");
}
template <int N> __device__ __forceinline__ void cp_wait() {
    asm volatile("cp.async.wait_group %0;" :: "n"(N));
}

// ---------------------------------------------------------------------------
// Pipelined NT GEMM via tf32 mma.sync (R3-proven geometry):
//   C[m,n] = sum_k Ain[m,k] * W[n,k] + bias[n]
// BM=BN=128, BK=16, 3-stage cp.async ring, 256 thr (8 warps 2x4, 64x32/warp).
// cvt.rna at fragment load (identity on pre-rounded data).
// out_mode: 0 -> plain fp32 C; 1/2/3 -> scatter tf32-ROUNDED to g_Q/g_K/g_V
// ---------------------------------------------------------------------------
#define RS 20           // smem row stride (floats); frag banks (4g+t) distinct
#define STG 3
#define KT (DD / 16)

struct GemmArgs {
    const float* A[3];
    const float* W[3];
    const float* bias[3];
    float* C;
    int out_mode[3];
};

__global__ __launch_bounds__(256, 2) void gemm_pipe_kernel(GemmArgs args)
{
    __shared__ float As[STG][128 * RS];
    __shared__ float Bs[STG][128 * RS];

    int z = blockIdx.z;
    const float* __restrict__ Ain  = args.A[z];
    const float* __restrict__ W    = args.W[z];
    const float* __restrict__ bias = args.bias[z];
    int out_mode = args.out_mode[z];

    int tid  = threadIdx.x;
    int lane = tid & 31;
    int w    = tid >> 5;
    int wm   = w >> 2;          // 0..1
    int wn   = w & 3;           // 0..3
    int g    = lane >> 2;       // 0..7
    int t    = lane & 3;        // 0..3

    int bm = blockIdx.y * 128;
    int bn = blockIdx.x * 128;

    int r0c = tid >> 1;
    int c0c = (tid & 1) * 8;

    float c[4][4][4];
#pragma unroll
    for (int mi = 0; mi < 4; mi++)
#pragma unroll
        for (int nj = 0; nj < 4; nj++)
#pragma unroll
            for (int e = 0; e < 4; e++) c[mi][nj][e] = 0.0f;

#pragma unroll
    for (int pf = 0; pf < STG - 1; pf++) {
        int k0 = pf * 16;
        cp_async16(&As[pf][r0c * RS + c0c],     &Ain[(size_t)(bm + r0c) * DD + k0 + c0c]);
        cp_async16(&As[pf][r0c * RS + c0c + 4], &Ain[(size_t)(bm + r0c) * DD + k0 + c0c + 4]);
        cp_async16(&Bs[pf][r0c * RS + c0c],     &W[(size_t)(bn + r0c) * DD + k0 + c0c]);
        cp_async16(&Bs[pf][r0c * RS + c0c + 4], &W[(size_t)(bn + r0c) * DD + k0 + c0c + 4]);
        cp_commit();
    }
    cp_wait<STG - 2>();
    __syncthreads();

    for (int kt = 0; kt < KT; kt++) {
        int st = kt % STG;

        if (kt + STG - 1 < KT) {
            int ps = (kt + STG - 1) % STG;
            int k0 = (kt + STG - 1) * 16;
            cp_async16(&As[ps][r0c * RS + c0c],     &Ain[(size_t)(bm + r0c) * DD + k0 + c0c]);
            cp_async16(&As[ps][r0c * RS + c0c + 4], &Ain[(size_t)(bm + r0c) * DD + k0 + c0c + 4]);
            cp_async16(&Bs[ps][r0c * RS + c0c],     &W[(size_t)(bn + r0c) * DD + k0 + c0c]);
            cp_async16(&Bs[ps][r0c * RS + c0c + 4], &W[(size_t)(bn + r0c) * DD + k0 + c0c + 4]);
        }
        cp_commit();

        const float* a_s = As[st];
        const float* b_s = Bs[st];
#pragma unroll
        for (int ks = 0; ks < 2; ks++) {
            unsigned af[4][4], bf[4][2];
#pragma unroll
            for (int mi = 0; mi < 4; mi++) {
                int m = wm * 64 + mi * 16 + g;
                af[mi][0] = f2tf32(a_s[m * RS + ks * 8 + t]);
                af[mi][1] = f2tf32(a_s[(m + 8) * RS + ks * 8 + t]);
                af[mi][2] = f2tf32(a_s[m * RS + ks * 8 + t + 4]);
                af[mi][3] = f2tf32(a_s[(m + 8) * RS + ks * 8 + t + 4]);
            }
#pragma unroll
            for (int nj = 0; nj < 4; nj++) {
                int n = wn * 32 + nj * 8 + g;
                bf[nj][0] = f2tf32(b_s[n * RS + ks * 8 + t]);
                bf[nj][1] = f2tf32(b_s[n * RS + ks * 8 + t + 4]);
            }
#pragma unroll
            for (int mi = 0; mi < 4; mi++)
#pragma unroll
                for (int nj = 0; nj < 4; nj++)
                    mma_tf32(c[mi][nj], af[mi], bf[nj]);
        }

        cp_wait<STG - 2>();
        __syncthreads();
    }

    // epilogue: bias + store
#pragma unroll
    for (int mi = 0; mi < 4; mi++) {
#pragma unroll
        for (int nj = 0; nj < 4; nj++) {
            int m = bm + wm * 64 + mi * 16 + g;
            int n = bn + wn * 32 + nj * 8 + 2 * t;
            float b0 = bias[n], b1 = bias[n + 1];
            if (out_mode == 0) {
                *(float2*)&args.C[(size_t)m * DD + n] =
                    make_float2(c[mi][nj][0] + b0, c[mi][nj][1] + b1);
                *(float2*)&args.C[(size_t)(m + 8) * DD + n] =
                    make_float2(c[mi][nj][2] + b0, c[mi][nj][3] + b1);
            } else {
                // round to tf32 so attention can consume raw bits
                float2 v0 = make_float2(f2tf32f(c[mi][nj][0] + b0), f2tf32f(c[mi][nj][1] + b1));
                float2 v1 = make_float2(f2tf32f(c[mi][nj][2] + b0), f2tf32f(c[mi][nj][3] + b1));
                int b  = m >> 11;
                int s  = m & (SS - 1);
                int h  = n >> 6;
                int dk = n & (DKK - 1);
                float* dst = (out_mode == 1) ? g_Q : (out_mode == 2) ? g_K : g_V;
                size_t base = (((size_t)(b * HH + h)) * SS) * DKK + dk;
                *(float2*)&dst[base + (size_t)s * DKK]  = v0;
                int s1 = (m + 8) & (SS - 1);
                *(float2*)&dst[base + (size_t)s1 * DKK] = v1;
            }
        }
    }
}

// ---------------------------------------------------------------------------
// Causal flash attention via tf32 mma.sync, K/V double-buffered cp.async.
// grid = (S/64, B*H), 128 threads (4 warps); warp owns 16 Q rows.
// Q/K/V pre-rounded tf32 -> raw-bit staging. qb reversed: heavy CTAs first.
// ---------------------------------------------------------------------------
#define SCALE_LOG2E 0.1803368801111244f   // (1/sqrt(64)) * log2(e)

__global__ __launch_bounds__(128) void attn_tc_kernel()
{
    __shared__ unsigned QPs[64][68];      // Q tile then P
    __shared__ float    Ks[2][64][68];    // double-buffered
    __shared__ float    Vs[2][64][72];

    int tid  = threadIdx.x;
    int lane = tid & 31;
    int w    = tid >> 5;
    int g    = lane >> 2;
    int t    = lane & 3;
    int wrow = w * 16;

    int qb = gridDim.x - 1 - blockIdx.x;  // heavy blocks first
    int bh = blockIdx.y;
    int b  = bh >> 4;
    int h  = bh & (HH - 1);
    size_t head = (size_t)bh * SS * DKK;

    // ---- stage Q tile (raw bits; already tf32-rounded) ----
#pragma unroll
    for (int it = 0; it < 8; it++) {
        int i  = it * 128 + tid;
        int r  = i >> 4;
        int c4 = (i & 15) << 2;
        float4 v4 = *(const float4*)&g_Q[head + (size_t)(qb * 64 + r) * DKK + c4];
        QPs[r][c4 + 0] = __float_as_uint(v4.x);
        QPs[r][c4 + 1] = __float_as_uint(v4.y);
        QPs[r][c4 + 2] = __float_as_uint(v4.z);
        QPs[r][c4 + 3] = __float_as_uint(v4.w);
    }

    // ---- prefetch K/V tile 0 into buffer 0 ----
#pragma unroll
    for (int it = 0; it < 8; it++) {
        int ch = it * 128 + tid;
        int r  = ch >> 4;
        int c4 = (ch & 15) << 2;
        size_t gi = head + (size_t)r * DKK + c4;
        cp_async16(&Ks[0][r][c4], &g_K[gi]);
        cp_async16(&Vs[0][r][c4], &g_V[gi]);
    }
    cp_commit();

    __syncthreads();

    // ---- Q fragments to registers ----
    unsigned qf[8][4];
#pragma unroll
    for (int ks = 0; ks < 8; ks++) {
        qf[ks][0] = QPs[wrow + g][ks * 8 + t];
        qf[ks][1] = QPs[wrow + g + 8][ks * 8 + t];
        qf[ks][2] = QPs[wrow + g][ks * 8 + t + 4];
        qf[ks][3] = QPs[wrow + g + 8][ks * 8 + t + 4];
    }

    float o[8][4];
#pragma unroll
    for (int nj = 0; nj < 8; nj++)
#pragma unroll
        for (int e = 0; e < 4; e++) o[nj][e] = 0.0f;
    float m0 = -1e30f, m1 = -1e30f, l0 = 0.0f, l1 = 0.0f;

    for (int j = 0; j <= qb; j++) {
        int cur = j & 1;
        __syncthreads();   // all warps done reading buffer (j+1)&1 / QPs

        // prefetch tile j+1 into the other buffer
        if (j < qb) {
            int nxt = (j + 1) & 1;
#pragma unroll
            for (int it = 0; it < 8; it++) {
                int ch = it * 128 + tid;
                int r  = ch >> 4;
                int c4 = (ch & 15) << 2;
                size_t gi = head + (size_t)((j + 1) * 64 + r) * DKK + c4;
                cp_async16(&Ks[nxt][r][c4], &g_K[gi]);
                cp_async16(&Vs[nxt][r][c4], &g_V[gi]);
            }
        }
        cp_commit();
        cp_wait<1>();      // tile j resident
        __syncthreads();

        // ---- S = Q @ K^T ----
        float s[8][4];
#pragma unroll
        for (int nj = 0; nj < 8; nj++)
#pragma unroll
            for (int e = 0; e < 4; e++) s[nj][e] = 0.0f;

#pragma unroll
        for (int ks = 0; ks < 8; ks++) {
#pragma unroll
            for (int nj = 0; nj < 8; nj++) {
                unsigned bf[2];
                bf[0] = __float_as_uint(Ks[cur][nj * 8 + g][ks * 8 + t]);
                bf[1] = __float_as_uint(Ks[cur][nj * 8 + g][ks * 8 + t + 4]);
                mma_tf32(s[nj], qf[ks], bf);
            }
        }

#pragma unroll
        for (int nj = 0; nj < 8; nj++)
#pragma unroll
            for (int e = 0; e < 4; e++) s[nj][e] *= SCALE_LOG2E;

        if (j == qb) {  // diagonal tile causal mask (local coords)
#pragma unroll
            for (int nj = 0; nj < 8; nj++) {
                int c0 = nj * 8 + 2 * t;
                if (c0     > wrow + g)     s[nj][0] = -1e30f;
                if (c0 + 1 > wrow + g)     s[nj][1] = -1e30f;
                if (c0     > wrow + g + 8) s[nj][2] = -1e30f;
                if (c0 + 1 > wrow + g + 8) s[nj][3] = -1e30f;
            }
        }

        float mx0 = -1e30f, mx1 = -1e30f;
#pragma unroll
        for (int nj = 0; nj < 8; nj++) {
            mx0 = fmaxf(mx0, fmaxf(s[nj][0], s[nj][1]));
            mx1 = fmaxf(mx1, fmaxf(s[nj][2], s[nj][3]));
        }
        mx0 = fmaxf(mx0, __shfl_xor_sync(0xffffffffu, mx0, 1));
        mx0 = fmaxf(mx0, __shfl_xor_sync(0xffffffffu, mx0, 2));
        mx1 = fmaxf(mx1, __shfl_xor_sync(0xffffffffu, mx1, 1));
        mx1 = fmaxf(mx1, __shfl_xor_sync(0xffffffffu, mx1, 2));

        float m0n = fmaxf(m0, mx0), m1n = fmaxf(m1, mx1);
        float a0 = ex2(m0 - m0n),   a1 = ex2(m1 - m1n);
        m0 = m0n; m1 = m1n;

        float rs0 = 0.0f, rs1 = 0.0f;
#pragma unroll
        for (int nj = 0; nj < 8; nj++) {
            float p;
            p = ex2(s[nj][0] - m0n); rs0 += p; s[nj][0] = p;
            p = ex2(s[nj][1] - m0n); rs0 += p; s[nj][1] = p;
            p = ex2(s[nj][2] - m1n); rs1 += p; s[nj][2] = p;
            p = ex2(s[nj][3] - m1n); rs1 += p; s[nj][3] = p;
        }
        rs0 += __shfl_xor_sync(0xffffffffu, rs0, 1);
        rs0 += __shfl_xor_sync(0xffffffffu, rs0, 2);
        rs1 += __shfl_xor_sync(0xffffffffu, rs1, 1);
        rs1 += __shfl_xor_sync(0xffffffffu, rs1, 2);

        l0 = l0 * a0 + rs0;
        l1 = l1 * a1 + rs1;
#pragma unroll
        for (int nj = 0; nj < 8; nj++) {
            o[nj][0] *= a0; o[nj][1] *= a0;
            o[nj][2] *= a1; o[nj][3] *= a1;
        }

        // ---- P -> smem (warp-private rows) ----
#pragma unroll
        for (int nj = 0; nj < 8; nj++) {
            int cc = nj * 8 + 2 * t;
            QPs[wrow + g][cc]         = f2tf32(s[nj][0]);
            QPs[wrow + g][cc + 1]     = f2tf32(s[nj][1]);
            QPs[wrow + g + 8][cc]     = f2tf32(s[nj][2]);
            QPs[wrow + g + 8][cc + 1] = f2tf32(s[nj][3]);
        }
        __syncwarp();

        // ---- O += P @ V ----
#pragma unroll
        for (int ks = 0; ks < 8; ks++) {
            unsigned pf[4];
            pf[0] = QPs[wrow + g][ks * 8 + t];
            pf[1] = QPs[wrow + g + 8][ks * 8 + t];
            pf[2] = QPs[wrow + g][ks * 8 + t + 4];
            pf[3] = QPs[wrow + g + 8][ks * 8 + t + 4];
#pragma unroll
            for (int nj = 0; nj < 8; nj++) {
                unsigned vf[2];
                vf[0] = __float_as_uint(Vs[cur][ks * 8 + t][nj * 8 + g]);
                vf[1] = __float_as_uint(Vs[cur][ks * 8 + t + 4][nj * 8 + g]);
                mma_tf32(o[nj], pf, vf);
            }
        }
    }

    // ---- epilogue: normalize + tf32-round (out-proj consumes these) ----
    float inv0 = 1.0f / l0, inv1 = 1.0f / l1;
    int row0 = qb * 64 + wrow + g;
    size_t base0 = ((size_t)(b * SS + row0)) * DD + h * 64;
    size_t base1 = base0 + (size_t)8 * DD;
#pragma unroll
    for (int nj = 0; nj < 8; nj++) {
        int cc = nj * 8 + 2 * t;
        *(float2*)&g_Ctx[base0 + cc] =
            make_float2(f2tf32f(o[nj][0] * inv0), f2tf32f(o[nj][1] * inv0));
        *(float2*)&g_Ctx[base1 + cc] =
            make_float2(f2tf32f(o[nj][2] * inv1), f2tf32f(o[nj][3] * inv1));
    }
}

// ---------------------------------------------------------------------------
// kernel_launch
// ---------------------------------------------------------------------------
extern "C" void kernel_launch(void* const* d_in, const int* in_sizes, int n_in,
                              void* d_out, int out_size)
{
    const float* q    = (const float*)d_in[0];
    const float* k    = (const float*)d_in[1];
    const float* v    = (const float*)d_in[2];
    const float* wq_w = (const float*)d_in[4];
    const float* wq_b = (const float*)d_in[5];
    const float* wk_w = (const float*)d_in[6];
    const float* wk_b = (const float*)d_in[7];
    const float* wv_w = (const float*)d_in[8];
    const float* wv_b = (const float*)d_in[9];
    const float* wo_w = (const float*)d_in[10];
    const float* wo_b = (const float*)d_in[11];
    float* out = (float*)d_out;

    void* p_ctx = nullptr;
    cudaGetSymbolAddress(&p_ctx, g_Ctx);

    // fused QKV projections (one launch, 3 GEMMs on z)
    GemmArgs qkv;
    qkv.A[0] = q;    qkv.A[1] = k;    qkv.A[2] = v;
    qkv.W[0] = wq_w; qkv.W[1] = wk_w; qkv.W[2] = wv_w;
    qkv.bias[0] = wq_b; qkv.bias[1] = wk_b; qkv.bias[2] = wv_b;
    qkv.C = nullptr;
    qkv.out_mode[0] = 1; qkv.out_mode[1] = 2; qkv.out_mode[2] = 3;
    gemm_pipe_kernel<<<dim3(DD / 128, MM / 128, 3), 256>>>(qkv);

    // attention
    attn_tc_kernel<<<dim3(SS / 64, BB * HH), 128>>>();

    // output projection
    GemmArgs og;
    og.A[0] = (const float*)p_ctx; og.A[1] = og.A[0]; og.A[2] = og.A[0];
    og.W[0] = wo_w; og.W[1] = wo_w; og.W[2] = wo_w;
    og.bias[0] = wo_b; og.bias[1] = wo_b; og.bias[2] = wo_b;
    og.C = out;
    og.out_mode[0] = 0; og.out_mode[1] = 0; og.out_mode[2] = 0;
    gemm_pipe_kernel<<<dim3(DD / 128, MM / 128, 1), 256>>>(og);
}

// round 10
// speedup vs baseline: 1.9120x; 1.6567x over previous
#include <cuda_runtime.h>
#include <cuda_fp16.h>
#include <math.h>

// Problem constants
#define BB 2
#define SS 2048
#define DD 1024
#define HH 16
#define DKK 64
#define MM (BB * SS)

// ---------------------------------------------------------------------------
// Scratch (device globals)
// ---------------------------------------------------------------------------
__device__ __half g_Qh[BB * HH * SS * DKK];   // [B,H,S,DK] fp16
__device__ __half g_Kh[BB * HH * SS * DKK];
__device__ __half g_Vh[BB * HH * SS * DKK];
__device__ __half g_Ctxh[BB * SS * DD];       // [B,S,D] fp16
__device__ __half g_qh[MM * DD];              // fp16 inputs
__device__ __half g_kh[MM * DD];
__device__ __half g_vh[MM * DD];
__device__ __half g_wh[4][DD * DD];           // fp16 weights q,k,v,o

// ---------------------------------------------------------------------------
// helpers
// ---------------------------------------------------------------------------
__device__ __forceinline__ float ex2(float x) {
    float y;
    asm("ex2.approx.f32 %0, %1;" : "=f"(y) : "f"(x));
    return y;
}

__device__ __forceinline__ void mma_f16(float* c, const unsigned* a, const unsigned* b) {
    asm volatile("mma.sync.aligned.m16n8k16.row.col.f32.f16.f16.f32 "
        "{%0,%1,%2,%3}, {%4,%5,%6,%7}, {%8,%9}, {%0,%1,%2,%3};"
        : "+f"(c[0]), "+f"(c[1]), "+f"(c[2]), "+f"(c[3])
        : "r"(a[0]), "r"(a[1]), "r"(a[2]), "r"(a[3]), "r"(b[0]), "r"(b[1]));
}

__device__ __forceinline__ unsigned smem_u32(const void* p) {
    return (unsigned)__cvta_generic_to_shared(p);
}
__device__ __forceinline__ void ldsm_x4(unsigned* r, unsigned addr) {
    asm volatile("ldmatrix.sync.aligned.m8n8.x4.shared.b16 {%0,%1,%2,%3}, [%4];"
        : "=r"(r[0]), "=r"(r[1]), "=r"(r[2]), "=r"(r[3]) : "r"(addr));
}
__device__ __forceinline__ void ldsm_x2_trans(unsigned* r, unsigned addr) {
    asm volatile("ldmatrix.sync.aligned.m8n8.x2.trans.shared.b16 {%0,%1}, [%2];"
        : "=r"(r[0]), "=r"(r[1]) : "r"(addr));
}

__device__ __forceinline__ void cp_async16(void* smem_dst, const void* gmem_src) {
    unsigned s = (unsigned)__cvta_generic_to_shared(smem_dst);
    asm volatile("cp.async.cg.shared.global [%0], [%1], 16;" :: "r"(s), "l"(gmem_src));
}
__device__ __forceinline__ void cp_commit() {
    asm volatile("cp.async.commit_group;");
}
template <int N> __device__ __forceinline__ void cp_wait() {
    asm volatile("cp.async.wait_group %0;" :: "n"(N));
}

// ---------------------------------------------------------------------------
// Prepass: fp32 -> fp16 conversion (inputs q,k,v + 4 weights)
// ---------------------------------------------------------------------------
struct F2HArgs {
    const float4* src[7];
    __half*       dst[7];
    int           n8[7];
};

__global__ __launch_bounds__(256) void f2h_kernel(F2HArgs a)
{
    int z = blockIdx.z;
    const float4* s = a.src[z];
    uint4* d = (uint4*)a.dst[z];
    int n8 = a.n8[z];
    int stride = gridDim.x * blockDim.x;
    for (int i = blockIdx.x * blockDim.x + threadIdx.x; i < n8; i += stride) {
        float4 x = s[2 * i], y = s[2 * i + 1];
        __half2 h0 = __floats2half2_rn(x.x, x.y);
        __half2 h1 = __floats2half2_rn(x.z, x.w);
        __half2 h2 = __floats2half2_rn(y.x, y.y);
        __half2 h3 = __floats2half2_rn(y.z, y.w);
        uint4 o;
        o.x = *(unsigned*)&h0; o.y = *(unsigned*)&h1;
        o.z = *(unsigned*)&h2; o.w = *(unsigned*)&h3;
        d[i] = o;
    }
}

// ---------------------------------------------------------------------------
// Pipelined NT GEMM via fp16 m16n8k16 mma.sync:
//   C[m,n] = sum_k Ain[m,k] * W[n,k] + bias[n]    (A, W fp16; accum fp32)
// BM=BN=128, BK=32 halfs, 3-stage cp.async ring, 256 thr (8 warps 2x4).
// Warp tile 64x32: 4x4 MMAs x 2 k-steps of 16.
// out_mode: 0 -> plain fp32 C; 1/2/3 -> scatter fp16 to g_Qh/g_Kh/g_Vh
// smem rows padded to 20 words (40 halfs): frag banks (20g+t) all distinct.
// ---------------------------------------------------------------------------
#define RW 20           // row stride in 32-bit words
#define STG 3
#define KT (DD / 32)    // 32 k-tiles

struct GemmArgs {
    const __half* A[3];
    const __half* W[3];
    const float*  bias[3];
    float* C;
    int out_mode[3];
};

__global__ __launch_bounds__(256, 2) void gemm_f16_kernel(GemmArgs args)
{
    __shared__ unsigned As[STG][128 * RW];
    __shared__ unsigned Bs[STG][128 * RW];

    int z = blockIdx.z;
    const __half* __restrict__ Ain  = args.A[z];
    const __half* __restrict__ W    = args.W[z];
    const float*  __restrict__ bias = args.bias[z];
    int out_mode = args.out_mode[z];

    int tid  = threadIdx.x;
    int lane = tid & 31;
    int w    = tid >> 5;
    int wm   = w >> 2;          // 0..1
    int wn   = w & 3;           // 0..3
    int g    = lane >> 2;       // 0..7
    int t    = lane & 3;        // 0..3

    int bm = blockIdx.y * 128;
    int bn = blockIdx.x * 128;

    int rowc = tid >> 1;        // 0..127
    int chc  = (tid & 1) * 2;   // chunks {0,1} or {2,3}

    float c[4][4][4];
#pragma unroll
    for (int mi = 0; mi < 4; mi++)
#pragma unroll
        for (int nj = 0; nj < 4; nj++)
#pragma unroll
            for (int e = 0; e < 4; e++) c[mi][nj][e] = 0.0f;

#pragma unroll
    for (int pf = 0; pf < STG - 1; pf++) {
        int k0 = pf * 32;
        cp_async16(&As[pf][rowc * RW + chc * 4],
                   &Ain[(size_t)(bm + rowc) * DD + k0 + chc * 8]);
        cp_async16(&As[pf][rowc * RW + chc * 4 + 4],
                   &Ain[(size_t)(bm + rowc) * DD + k0 + chc * 8 + 8]);
        cp_async16(&Bs[pf][rowc * RW + chc * 4],
                   &W[(size_t)(bn + rowc) * DD + k0 + chc * 8]);
        cp_async16(&Bs[pf][rowc * RW + chc * 4 + 4],
                   &W[(size_t)(bn + rowc) * DD + k0 + chc * 8 + 8]);
        cp_commit();
    }
    cp_wait<STG - 2>();
    __syncthreads();

    for (int kt = 0; kt < KT; kt++) {
        int st = kt % STG;

        if (kt + STG - 1 < KT) {
            int ps = (kt + STG - 1) % STG;
            int k0 = (kt + STG - 1) * 32;
            cp_async16(&As[ps][rowc * RW + chc * 4],
                       &Ain[(size_t)(bm + rowc) * DD + k0 + chc * 8]);
            cp_async16(&As[ps][rowc * RW + chc * 4 + 4],
                       &Ain[(size_t)(bm + rowc) * DD + k0 + chc * 8 + 8]);
            cp_async16(&Bs[ps][rowc * RW + chc * 4],
                       &W[(size_t)(bn + rowc) * DD + k0 + chc * 8]);
            cp_async16(&Bs[ps][rowc * RW + chc * 4 + 4],
                       &W[(size_t)(bn + rowc) * DD + k0 + chc * 8 + 8]);
        }
        cp_commit();

        const unsigned* a_s = As[st];
        const unsigned* b_s = Bs[st];
#pragma unroll
        for (int ks = 0; ks < 2; ks++) {
            unsigned af[4][4], bf[4][2];
#pragma unroll
            for (int mi = 0; mi < 4; mi++) {
                int m = wm * 64 + mi * 16 + g;
                af[mi][0] = a_s[m * RW + ks * 8 + t];
                af[mi][1] = a_s[(m + 8) * RW + ks * 8 + t];
                af[mi][2] = a_s[m * RW + ks * 8 + t + 4];
                af[mi][3] = a_s[(m + 8) * RW + ks * 8 + t + 4];
            }
#pragma unroll
            for (int nj = 0; nj < 4; nj++) {
                int n = wn * 32 + nj * 8 + g;
                bf[nj][0] = b_s[n * RW + ks * 8 + t];
                bf[nj][1] = b_s[n * RW + ks * 8 + t + 4];
            }
#pragma unroll
            for (int mi = 0; mi < 4; mi++)
#pragma unroll
                for (int nj = 0; nj < 4; nj++)
                    mma_f16(c[mi][nj], af[mi], bf[nj]);
        }

        cp_wait<STG - 2>();
        __syncthreads();
    }

    // epilogue: bias + store
#pragma unroll
    for (int mi = 0; mi < 4; mi++) {
#pragma unroll
        for (int nj = 0; nj < 4; nj++) {
            int m = bm + wm * 64 + mi * 16 + g;
            int n = bn + wn * 32 + nj * 8 + 2 * t;
            float b0 = bias[n], b1 = bias[n + 1];
            if (out_mode == 0) {
                *(float2*)&args.C[(size_t)m * DD + n] =
                    make_float2(c[mi][nj][0] + b0, c[mi][nj][1] + b1);
                *(float2*)&args.C[(size_t)(m + 8) * DD + n] =
                    make_float2(c[mi][nj][2] + b0, c[mi][nj][3] + b1);
            } else {
                __half2 v0 = __floats2half2_rn(c[mi][nj][0] + b0, c[mi][nj][1] + b1);
                __half2 v1 = __floats2half2_rn(c[mi][nj][2] + b0, c[mi][nj][3] + b1);
                int b  = m >> 11;
                int s  = m & (SS - 1);
                int h  = n >> 6;
                int dk = n & (DKK - 1);
                __half* dst = (out_mode == 1) ? g_Qh : (out_mode == 2) ? g_Kh : g_Vh;
                size_t base = (((size_t)(b * HH + h)) * SS) * DKK + dk;
                *(__half2*)&dst[base + (size_t)s * DKK]  = v0;
                int s1 = (m + 8) & (SS - 1);
                *(__half2*)&dst[base + (size_t)s1 * DKK] = v1;
            }
        }
    }
}

// ---------------------------------------------------------------------------
// Causal flash attention via fp16 m16n8k16 mma.sync.
// grid=(S/64, B*H), 128 thr (4 warps); warp owns 16 Q rows.
// K/V double-buffered cp.async; Q/P frags via ldmatrix x4; K frags scalar
// LDS (contiguous half2); V frags via ldmatrix.x2.trans. Softmax fp32.
// ---------------------------------------------------------------------------
#define SCALE_LOG2E 0.1803368801111244f   // (1/sqrt(64)) * log2(e)
#define AR 72                              // attention smem row stride (halfs)

__global__ __launch_bounds__(128) void attn_f16_kernel()
{
    __shared__ __half QPs[64][AR];        // Q tile then P (9.2 KB)
    __shared__ __half Ks[2][64][AR];      // 18.4 KB
    __shared__ __half Vs[2][64][AR];      // 18.4 KB

    int tid  = threadIdx.x;
    int lane = tid & 31;
    int w    = tid >> 5;
    int g    = lane >> 2;
    int t    = lane & 3;
    int wrow = w * 16;

    int qb = gridDim.x - 1 - blockIdx.x;  // heavy blocks first
    int bh = blockIdx.y;
    int b  = bh >> 4;
    int h  = bh & (HH - 1);
    size_t head = (size_t)bh * SS * DKK;

    // per-lane ldmatrix base addresses
    // Q/P x4: lanes 0-7 rows wrow+0..7 col 0; 8-15 rows +8..15 col 0;
    //         16-23 rows 0..7 col 8; 24-31 rows 8..15 col 8
    int qrow = wrow + (lane & 7) + ((lane >> 3) & 1) * 8;
    int qcol = (lane >> 4) * 8;
    unsigned qp_lane = smem_u32(&QPs[qrow][qcol]);
    // V x2.trans: lanes 0-15 = rows (lane&15) of the k-block
    unsigned v_lane0 = smem_u32(&Vs[0][lane & 15][0]);
    unsigned v_lane1 = smem_u32(&Vs[1][lane & 15][0]);

    // ---- stage Q tile [64][64] halfs ----
#pragma unroll
    for (int it = 0; it < 4; it++) {
        int i  = it * 128 + tid;
        int r  = i >> 3;
        int c8 = (i & 7) << 3;
        *(uint4*)&QPs[r][c8] =
            *(const uint4*)&g_Qh[head + (size_t)(qb * 64 + r) * DKK + c8];
    }

    // ---- prefetch K/V tile 0 into buffer 0 ----
#pragma unroll
    for (int it = 0; it < 4; it++) {
        int i  = it * 128 + tid;
        int r  = i >> 3;
        int c8 = (i & 7) << 3;
        size_t gi = head + (size_t)r * DKK + c8;
        cp_async16(&Ks[0][r][c8], &g_Kh[gi]);
        cp_async16(&Vs[0][r][c8], &g_Vh[gi]);
    }
    cp_commit();
    __syncthreads();

    // ---- Q fragments to registers (4 k-steps of 16) ----
    unsigned qf[4][4];
#pragma unroll
    for (int ks = 0; ks < 4; ks++)
        ldsm_x4(qf[ks], qp_lane + ks * 32);   // 16 halfs = 32 bytes

    float o[8][4];
#pragma unroll
    for (int nj = 0; nj < 8; nj++)
#pragma unroll
        for (int e = 0; e < 4; e++) o[nj][e] = 0.0f;
    float m0 = -1e30f, m1 = -1e30f, l0 = 0.0f, l1 = 0.0f;

    for (int j = 0; j <= qb; j++) {
        int cur = j & 1;
        __syncthreads();   // done reading buffer (j+1)&1 / QPs

        if (j < qb) {
            int nxt = (j + 1) & 1;
#pragma unroll
            for (int it = 0; it < 4; it++) {
                int i  = it * 128 + tid;
                int r  = i >> 3;
                int c8 = (i & 7) << 3;
                size_t gi = head + (size_t)((j + 1) * 64 + r) * DKK + c8;
                cp_async16(&Ks[nxt][r][c8], &g_Kh[gi]);
                cp_async16(&Vs[nxt][r][c8], &g_Vh[gi]);
            }
        }
        cp_commit();
        cp_wait<1>();      // tile j resident
        __syncthreads();

        // ---- S = Q @ K^T  (K frags: contiguous half2 scalar LDS) ----
        float s[8][4];
#pragma unroll
        for (int nj = 0; nj < 8; nj++)
#pragma unroll
            for (int e = 0; e < 4; e++) s[nj][e] = 0.0f;

#pragma unroll
        for (int ks = 0; ks < 4; ks++) {
#pragma unroll
            for (int nj = 0; nj < 8; nj++) {
                unsigned bf[2];
                bf[0] = *(const unsigned*)&Ks[cur][nj * 8 + g][ks * 16 + 2 * t];
                bf[1] = *(const unsigned*)&Ks[cur][nj * 8 + g][ks * 16 + 2 * t + 8];
                mma_f16(s[nj], qf[ks], bf);
            }
        }

#pragma unroll
        for (int nj = 0; nj < 8; nj++)
#pragma unroll
            for (int e = 0; e < 4; e++) s[nj][e] *= SCALE_LOG2E;

        if (j == qb) {  // diagonal tile causal mask (local coords)
#pragma unroll
            for (int nj = 0; nj < 8; nj++) {
                int c0 = nj * 8 + 2 * t;
                if (c0     > wrow + g)     s[nj][0] = -1e30f;
                if (c0 + 1 > wrow + g)     s[nj][1] = -1e30f;
                if (c0     > wrow + g + 8) s[nj][2] = -1e30f;
                if (c0 + 1 > wrow + g + 8) s[nj][3] = -1e30f;
            }
        }

        float mx0 = -1e30f, mx1 = -1e30f;
#pragma unroll
        for (int nj = 0; nj < 8; nj++) {
            mx0 = fmaxf(mx0, fmaxf(s[nj][0], s[nj][1]));
            mx1 = fmaxf(mx1, fmaxf(s[nj][2], s[nj][3]));
        }
        mx0 = fmaxf(mx0, __shfl_xor_sync(0xffffffffu, mx0, 1));
        mx0 = fmaxf(mx0, __shfl_xor_sync(0xffffffffu, mx0, 2));
        mx1 = fmaxf(mx1, __shfl_xor_sync(0xffffffffu, mx1, 1));
        mx1 = fmaxf(mx1, __shfl_xor_sync(0xffffffffu, mx1, 2));

        float m0n = fmaxf(m0, mx0), m1n = fmaxf(m1, mx1);
        float a0 = ex2(m0 - m0n),   a1 = ex2(m1 - m1n);
        m0 = m0n; m1 = m1n;

        float rs0 = 0.0f, rs1 = 0.0f;
#pragma unroll
        for (int nj = 0; nj < 8; nj++) {
            float p;
            p = ex2(s[nj][0] - m0n); rs0 += p; s[nj][0] = p;
            p = ex2(s[nj][1] - m0n); rs0 += p; s[nj][1] = p;
            p = ex2(s[nj][2] - m1n); rs1 += p; s[nj][2] = p;
            p = ex2(s[nj][3] - m1n); rs1 += p; s[nj][3] = p;
        }
        rs0 += __shfl_xor_sync(0xffffffffu, rs0, 1);
        rs0 += __shfl_xor_sync(0xffffffffu, rs0, 2);
        rs1 += __shfl_xor_sync(0xffffffffu, rs1, 1);
        rs1 += __shfl_xor_sync(0xffffffffu, rs1, 2);

        l0 = l0 * a0 + rs0;
        l1 = l1 * a1 + rs1;
#pragma unroll
        for (int nj = 0; nj < 8; nj++) {
            o[nj][0] *= a0; o[nj][1] *= a0;
            o[nj][2] *= a1; o[nj][3] *= a1;
        }

        // ---- P -> smem as fp16 (warp-private rows) ----
#pragma unroll
        for (int nj = 0; nj < 8; nj++) {
            int cc = nj * 8 + 2 * t;
            *(__half2*)&QPs[wrow + g][cc]     = __floats2half2_rn(s[nj][0], s[nj][1]);
            *(__half2*)&QPs[wrow + g + 8][cc] = __floats2half2_rn(s[nj][2], s[nj][3]);
        }
        __syncwarp();

        // ---- O += P @ V  (P via ldmatrix x4; V via ldmatrix x2.trans) ----
        unsigned v_base = cur ? v_lane1 : v_lane0;
#pragma unroll
        for (int ks = 0; ks < 4; ks++) {
            unsigned pf[4];
            ldsm_x4(pf, qp_lane + ks * 32);
#pragma unroll
            for (int nj = 0; nj < 8; nj++) {
                unsigned vf[2];
                ldsm_x2_trans(vf, v_base + (unsigned)(ks * 16 * AR + nj * 8) * 2u);
                mma_f16(o[nj], pf, vf);
            }
        }
    }

    // ---- epilogue: normalize + fp16 (out-proj consumes these) ----
    float inv0 = 1.0f / l0, inv1 = 1.0f / l1;
    int row0 = qb * 64 + wrow + g;
    size_t base0 = ((size_t)(b * SS + row0)) * DD + h * 64;
    size_t base1 = base0 + (size_t)8 * DD;
#pragma unroll
    for (int nj = 0; nj < 8; nj++) {
        int cc = nj * 8 + 2 * t;
        *(__half2*)&g_Ctxh[base0 + cc] = __floats2half2_rn(o[nj][0] * inv0, o[nj][1] * inv0);
        *(__half2*)&g_Ctxh[base1 + cc] = __floats2half2_rn(o[nj][2] * inv1, o[nj][3] * inv1);
    }
}

// ---------------------------------------------------------------------------
// kernel_launch
// ---------------------------------------------------------------------------
extern "C" void kernel_launch(void* const* d_in, const int* in_sizes, int n_in,
                              void* d_out, int out_size)
{
    const float* q    = (const float*)d_in[0];
    const float* k    = (const float*)d_in[1];
    const float* v    = (const float*)d_in[2];
    const float* wq_w = (const float*)d_in[4];
    const float* wq_b = (const float*)d_in[5];
    const float* wk_w = (const float*)d_in[6];
    const float* wk_b = (const float*)d_in[7];
    const float* wv_w = (const float*)d_in[8];
    const float* wv_b = (const float*)d_in[9];
    const float* wo_w = (const float*)d_in[10];
    const float* wo_b = (const float*)d_in[11];
    float* out = (float*)d_out;

    void *p_qh, *p_kh, *p_vh, *p_wh, *p_ctxh;
    cudaGetSymbolAddress(&p_qh, g_qh);
    cudaGetSymbolAddress(&p_kh, g_kh);
    cudaGetSymbolAddress(&p_vh, g_vh);
    cudaGetSymbolAddress(&p_wh, g_wh);
    cudaGetSymbolAddress(&p_ctxh, g_Ctxh);
    __half* w0 = (__half*)p_wh;
    __half* w1 = w0 + DD * DD;
    __half* w2 = w0 + 2 * DD * DD;
    __half* w3 = w0 + 3 * DD * DD;

    // prepass: convert inputs + weights to fp16
    F2HArgs fa;
    fa.src[0] = (const float4*)q;    fa.dst[0] = (__half*)p_qh; fa.n8[0] = MM * DD / 8;
    fa.src[1] = (const float4*)k;    fa.dst[1] = (__half*)p_kh; fa.n8[1] = MM * DD / 8;
    fa.src[2] = (const float4*)v;    fa.dst[2] = (__half*)p_vh; fa.n8[2] = MM * DD / 8;
    fa.src[3] = (const float4*)wq_w; fa.dst[3] = w0;            fa.n8[3] = DD * DD / 8;
    fa.src[4] = (const float4*)wk_w; fa.dst[4] = w1;            fa.n8[4] = DD * DD / 8;
    fa.src[5] = (const float4*)wv_w; fa.dst[5] = w2;            fa.n8[5] = DD * DD / 8;
    fa.src[6] = (const float4*)wo_w; fa.dst[6] = w3;            fa.n8[6] = DD * DD / 8;
    f2h_kernel<<<dim3(128, 1, 7), 256>>>(fa);

    // fused QKV projections (fp16 MMA)
    GemmArgs qkv;
    qkv.A[0] = (const __half*)p_qh; qkv.A[1] = (const __half*)p_kh; qkv.A[2] = (const __half*)p_vh;
    qkv.W[0] = w0; qkv.W[1] = w1; qkv.W[2] = w2;
    qkv.bias[0] = wq_b; qkv.bias[1] = wk_b; qkv.bias[2] = wv_b;
    qkv.C = nullptr;
    qkv.out_mode[0] = 1; qkv.out_mode[1] = 2; qkv.out_mode[2] = 3;
    gemm_f16_kernel<<<dim3(DD / 128, MM / 128, 3), 256>>>(qkv);

    // attention
    attn_f16_kernel<<<dim3(SS / 64, BB * HH), 128>>>();

    // output projection (A = g_Ctxh fp16)
    GemmArgs og;
    og.A[0] = (const __half*)p_ctxh; og.A[1] = og.A[0]; og.A[2] = og.A[0];
    og.W[0] = w3; og.W[1] = w3; og.W[2] = w3;
    og.bias[0] = wo_b; og.bias[1] = wo_b; og.bias[2] = wo_b;
    og.C = out;
    og.out_mode[0] = 0; og.out_mode[1] = 0; og.out_mode[2] = 0;
    gemm_f16_kernel<<<dim3(DD / 128, MM / 128, 1), 256>>>(og);
}

// round 11
// speedup vs baseline: 2.1325x; 1.1153x over previous
#include <cuda_runtime.h>
#include <cuda_fp16.h>
#include <math.h>

// Problem constants
#define BB 2
#define SS 2048
#define DD 1024
#define HH 16
#define DKK 64
#define MM (BB * SS)

// ---------------------------------------------------------------------------
// Scratch (device globals)
// ---------------------------------------------------------------------------
__device__ __half g_Qh[BB * HH * SS * DKK];   // [B,H,S,DK] fp16
__device__ __half g_Kh[BB * HH * SS * DKK];
__device__ __half g_Vh[BB * HH * SS * DKK];
__device__ __half g_Ctxh[BB * SS * DD];       // [B,S,D] fp16
__device__ __half g_qh[MM * DD];              // fp16 inputs
__device__ __half g_kh[MM * DD];
__device__ __half g_vh[MM * DD];
__device__ __half g_wh[4][DD * DD];           // fp16 weights q,k,v,o

// ---------------------------------------------------------------------------
// helpers
// ---------------------------------------------------------------------------
__device__ __forceinline__ float ex2(float x) {
    float y;
    asm("ex2.approx.f32 %0, %1;" : "=f"(y) : "f"(x));
    return y;
}

__device__ __forceinline__ void mma_f16(float* c, const unsigned* a, const unsigned* b) {
    asm volatile("mma.sync.aligned.m16n8k16.row.col.f32.f16.f16.f32 "
        "{%0,%1,%2,%3}, {%4,%5,%6,%7}, {%8,%9}, {%0,%1,%2,%3};"
        : "+f"(c[0]), "+f"(c[1]), "+f"(c[2]), "+f"(c[3])
        : "r"(a[0]), "r"(a[1]), "r"(a[2]), "r"(a[3]), "r"(b[0]), "r"(b[1]));
}

__device__ __forceinline__ unsigned smem_u32(const void* p) {
    return (unsigned)__cvta_generic_to_shared(p);
}
__device__ __forceinline__ void ldsm_x4(unsigned* r, unsigned addr) {
    asm volatile("ldmatrix.sync.aligned.m8n8.x4.shared.b16 {%0,%1,%2,%3}, [%4];"
        : "=r"(r[0]), "=r"(r[1]), "=r"(r[2]), "=r"(r[3]) : "r"(addr));
}
__device__ __forceinline__ void ldsm_x2_trans(unsigned* r, unsigned addr) {
    asm volatile("ldmatrix.sync.aligned.m8n8.x2.trans.shared.b16 {%0,%1}, [%2];"
        : "=r"(r[0]), "=r"(r[1]) : "r"(addr));
}

__device__ __forceinline__ void cp_async16(void* smem_dst, const void* gmem_src) {
    unsigned s = (unsigned)__cvta_generic_to_shared(smem_dst);
    asm volatile("cp.async.cg.shared.global [%0], [%1], 16;" :: "r"(s), "l"(gmem_src));
}
__device__ __forceinline__ void cp_commit() {
    asm volatile("cp.async.commit_group;");
}
template <int N> __device__ __forceinline__ void cp_wait() {
    asm volatile("cp.async.wait_group %0;" :: "n"(N));
}

// ---------------------------------------------------------------------------
// Prepass: fp32 -> fp16 conversion (inputs q,k,v + 4 weights)
// ---------------------------------------------------------------------------
struct F2HArgs {
    const float4* src[7];
    __half*       dst[7];
    int           n8[7];
};

__global__ __launch_bounds__(256) void f2h_kernel(F2HArgs a)
{
    int z = blockIdx.z;
    const float4* s = a.src[z];
    uint4* d = (uint4*)a.dst[z];
    int n8 = a.n8[z];
    int stride = gridDim.x * blockDim.x;
    for (int i = blockIdx.x * blockDim.x + threadIdx.x; i < n8; i += stride) {
        float4 x = s[2 * i], y = s[2 * i + 1];
        __half2 h0 = __floats2half2_rn(x.x, x.y);
        __half2 h1 = __floats2half2_rn(x.z, x.w);
        __half2 h2 = __floats2half2_rn(y.x, y.y);
        __half2 h3 = __floats2half2_rn(y.z, y.w);
        uint4 o;
        o.x = *(unsigned*)&h0; o.y = *(unsigned*)&h1;
        o.z = *(unsigned*)&h2; o.w = *(unsigned*)&h3;
        d[i] = o;
    }
}

// ---------------------------------------------------------------------------
// Pipelined NT GEMM via fp16 m16n8k16 mma.sync:
//   C[m,n] = sum_k Ain[m,k] * W[n,k] + bias[n]    (A, W fp16; accum fp32)
// BM=BN=128, BK=32 halfs, 3-stage cp.async ring, 128 thr = 4 warps (2x2).
// Warp tile 64x64: 4(m) x 8(n) MMAs x 2 k-steps of 16 = 64 MMA/warp/ktile.
// out_mode: 0 -> plain fp32 C; 1/2/3 -> scatter fp16 to g_Qh/g_Kh/g_Vh
// smem rows 20 words (32 halfs + pad): frag banks (4g+t)%32 all distinct.
// ---------------------------------------------------------------------------
#define RW 20           // row stride in 32-bit words
#define STG 3
#define KT (DD / 32)    // 32 k-tiles

struct GemmArgs {
    const __half* A[3];
    const __half* W[3];
    const float*  bias[3];
    float* C;
    int out_mode[3];
};

__global__ __launch_bounds__(128, 3) void gemm_f16_kernel(GemmArgs args)
{
    __shared__ unsigned As[STG][128 * RW];
    __shared__ unsigned Bs[STG][128 * RW];

    int z = blockIdx.z;
    const __half* __restrict__ Ain  = args.A[z];
    const __half* __restrict__ W    = args.W[z];
    const float*  __restrict__ bias = args.bias[z];
    int out_mode = args.out_mode[z];

    int tid  = threadIdx.x;
    int lane = tid & 31;
    int w    = tid >> 5;        // 0..3
    int wm   = w >> 1;          // 0..1 (64 rows)
    int wn   = w & 1;           // 0..1 (64 cols)
    int g    = lane >> 2;       // 0..7
    int t    = lane & 3;        // 0..3

    int bm = blockIdx.y * 128;
    int bn = blockIdx.x * 128;

    // staging: 128 rows x 4 chunks of 16B per matrix; 4 chunks per thread
    int rowc = tid >> 2;        // wrong span with 128 thr -> use idx loop below

    float c[4][8][4];
#pragma unroll
    for (int mi = 0; mi < 4; mi++)
#pragma unroll
        for (int nj = 0; nj < 8; nj++)
#pragma unroll
            for (int e = 0; e < 4; e++) c[mi][nj][e] = 0.0f;

    // prefetch stages 0..STG-2
#pragma unroll
    for (int pf = 0; pf < STG - 1; pf++) {
        int k0 = pf * 32;
#pragma unroll
        for (int it = 0; it < 4; it++) {
            int idx = it * 128 + tid;       // 0..511
            int row = idx >> 2;
            int ch  = idx & 3;
            cp_async16(&As[pf][row * RW + ch * 4],
                       &Ain[(size_t)(bm + row) * DD + k0 + ch * 8]);
            cp_async16(&Bs[pf][row * RW + ch * 4],
                       &W[(size_t)(bn + row) * DD + k0 + ch * 8]);
        }
        cp_commit();
    }
    cp_wait<STG - 2>();
    __syncthreads();

    for (int kt = 0; kt < KT; kt++) {
        int st = kt % STG;

        if (kt + STG - 1 < KT) {
            int ps = (kt + STG - 1) % STG;
            int k0 = (kt + STG - 1) * 32;
#pragma unroll
            for (int it = 0; it < 4; it++) {
                int idx = it * 128 + tid;
                int row = idx >> 2;
                int ch  = idx & 3;
                cp_async16(&As[ps][row * RW + ch * 4],
                           &Ain[(size_t)(bm + row) * DD + k0 + ch * 8]);
                cp_async16(&Bs[ps][row * RW + ch * 4],
                           &W[(size_t)(bn + row) * DD + k0 + ch * 8]);
            }
        }
        cp_commit();

        const unsigned* a_s = As[st];
        const unsigned* b_s = Bs[st];
#pragma unroll
        for (int ks = 0; ks < 2; ks++) {
            unsigned af[4][4], bf[8][2];
#pragma unroll
            for (int mi = 0; mi < 4; mi++) {
                int m = wm * 64 + mi * 16 + g;
                af[mi][0] = a_s[m * RW + ks * 8 + t];
                af[mi][1] = a_s[(m + 8) * RW + ks * 8 + t];
                af[mi][2] = a_s[m * RW + ks * 8 + t + 4];
                af[mi][3] = a_s[(m + 8) * RW + ks * 8 + t + 4];
            }
#pragma unroll
            for (int nj = 0; nj < 8; nj++) {
                int n = wn * 64 + nj * 8 + g;
                bf[nj][0] = b_s[n * RW + ks * 8 + t];
                bf[nj][1] = b_s[n * RW + ks * 8 + t + 4];
            }
#pragma unroll
            for (int mi = 0; mi < 4; mi++)
#pragma unroll
                for (int nj = 0; nj < 8; nj++)
                    mma_f16(c[mi][nj], af[mi], bf[nj]);
        }

        cp_wait<STG - 2>();
        __syncthreads();
    }

    // epilogue: bias + store
#pragma unroll
    for (int mi = 0; mi < 4; mi++) {
#pragma unroll
        for (int nj = 0; nj < 8; nj++) {
            int m = bm + wm * 64 + mi * 16 + g;
            int n = bn + wn * 64 + nj * 8 + 2 * t;
            float b0 = bias[n], b1 = bias[n + 1];
            if (out_mode == 0) {
                *(float2*)&args.C[(size_t)m * DD + n] =
                    make_float2(c[mi][nj][0] + b0, c[mi][nj][1] + b1);
                *(float2*)&args.C[(size_t)(m + 8) * DD + n] =
                    make_float2(c[mi][nj][2] + b0, c[mi][nj][3] + b1);
            } else {
                __half2 v0 = __floats2half2_rn(c[mi][nj][0] + b0, c[mi][nj][1] + b1);
                __half2 v1 = __floats2half2_rn(c[mi][nj][2] + b0, c[mi][nj][3] + b1);
                int b  = m >> 11;
                int s  = m & (SS - 1);
                int h  = n >> 6;
                int dk = n & (DKK - 1);
                __half* dst = (out_mode == 1) ? g_Qh : (out_mode == 2) ? g_Kh : g_Vh;
                size_t base = (((size_t)(b * HH + h)) * SS) * DKK + dk;
                *(__half2*)&dst[base + (size_t)s * DKK]  = v0;
                int s1 = (m + 8) & (SS - 1);
                *(__half2*)&dst[base + (size_t)s1 * DKK] = v1;
            }
        }
    }
    (void)rowc;
}

// ---------------------------------------------------------------------------
// Causal flash attention via fp16 m16n8k16 mma.sync (unchanged from R9).
// ---------------------------------------------------------------------------
#define SCALE_LOG2E 0.1803368801111244f   // (1/sqrt(64)) * log2(e)
#define AR 72                              // attention smem row stride (halfs)

__global__ __launch_bounds__(128) void attn_f16_kernel()
{
    __shared__ __half QPs[64][AR];
    __shared__ __half Ks[2][64][AR];
    __shared__ __half Vs[2][64][AR];

    int tid  = threadIdx.x;
    int lane = tid & 31;
    int w    = tid >> 5;
    int g    = lane >> 2;
    int t    = lane & 3;
    int wrow = w * 16;

    int qb = gridDim.x - 1 - blockIdx.x;
    int bh = blockIdx.y;
    int b  = bh >> 4;
    int h  = bh & (HH - 1);
    size_t head = (size_t)bh * SS * DKK;

    int qrow = wrow + (lane & 7) + ((lane >> 3) & 1) * 8;
    int qcol = (lane >> 4) * 8;
    unsigned qp_lane = smem_u32(&QPs[qrow][qcol]);
    unsigned v_lane0 = smem_u32(&Vs[0][lane & 15][0]);
    unsigned v_lane1 = smem_u32(&Vs[1][lane & 15][0]);

#pragma unroll
    for (int it = 0; it < 4; it++) {
        int i  = it * 128 + tid;
        int r  = i >> 3;
        int c8 = (i & 7) << 3;
        *(uint4*)&QPs[r][c8] =
            *(const uint4*)&g_Qh[head + (size_t)(qb * 64 + r) * DKK + c8];
    }

#pragma unroll
    for (int it = 0; it < 4; it++) {
        int i  = it * 128 + tid;
        int r  = i >> 3;
        int c8 = (i & 7) << 3;
        size_t gi = head + (size_t)r * DKK + c8;
        cp_async16(&Ks[0][r][c8], &g_Kh[gi]);
        cp_async16(&Vs[0][r][c8], &g_Vh[gi]);
    }
    cp_commit();
    __syncthreads();

    unsigned qf[4][4];
#pragma unroll
    for (int ks = 0; ks < 4; ks++)
        ldsm_x4(qf[ks], qp_lane + ks * 32);

    float o[8][4];
#pragma unroll
    for (int nj = 0; nj < 8; nj++)
#pragma unroll
        for (int e = 0; e < 4; e++) o[nj][e] = 0.0f;
    float m0 = -1e30f, m1 = -1e30f, l0 = 0.0f, l1 = 0.0f;

    for (int j = 0; j <= qb; j++) {
        int cur = j & 1;
        __syncthreads();

        if (j < qb) {
            int nxt = (j + 1) & 1;
#pragma unroll
            for (int it = 0; it < 4; it++) {
                int i  = it * 128 + tid;
                int r  = i >> 3;
                int c8 = (i & 7) << 3;
                size_t gi = head + (size_t)((j + 1) * 64 + r) * DKK + c8;
                cp_async16(&Ks[nxt][r][c8], &g_Kh[gi]);
                cp_async16(&Vs[nxt][r][c8], &g_Vh[gi]);
            }
        }
        cp_commit();
        cp_wait<1>();
        __syncthreads();

        float s[8][4];
#pragma unroll
        for (int nj = 0; nj < 8; nj++)
#pragma unroll
            for (int e = 0; e < 4; e++) s[nj][e] = 0.0f;

#pragma unroll
        for (int ks = 0; ks < 4; ks++) {
#pragma unroll
            for (int nj = 0; nj < 8; nj++) {
                unsigned bf[2];
                bf[0] = *(const unsigned*)&Ks[cur][nj * 8 + g][ks * 16 + 2 * t];
                bf[1] = *(const unsigned*)&Ks[cur][nj * 8 + g][ks * 16 + 2 * t + 8];
                mma_f16(s[nj], qf[ks], bf);
            }
        }

#pragma unroll
        for (int nj = 0; nj < 8; nj++)
#pragma unroll
            for (int e = 0; e < 4; e++) s[nj][e] *= SCALE_LOG2E;

        if (j == qb) {
#pragma unroll
            for (int nj = 0; nj < 8; nj++) {
                int c0 = nj * 8 + 2 * t;
                if (c0     > wrow + g)     s[nj][0] = -1e30f;
                if (c0 + 1 > wrow + g)     s[nj][1] = -1e30f;
                if (c0     > wrow + g + 8) s[nj][2] = -1e30f;
                if (c0 + 1 > wrow + g + 8) s[nj][3] = -1e30f;
            }
        }

        float mx0 = -1e30f, mx1 = -1e30f;
#pragma unroll
        for (int nj = 0; nj < 8; nj++) {
            mx0 = fmaxf(mx0, fmaxf(s[nj][0], s[nj][1]));
            mx1 = fmaxf(mx1, fmaxf(s[nj][2], s[nj][3]));
        }
        mx0 = fmaxf(mx0, __shfl_xor_sync(0xffffffffu, mx0, 1));
        mx0 = fmaxf(mx0, __shfl_xor_sync(0xffffffffu, mx0, 2));
        mx1 = fmaxf(mx1, __shfl_xor_sync(0xffffffffu, mx1, 1));
        mx1 = fmaxf(mx1, __shfl_xor_sync(0xffffffffu, mx1, 2));

        float m0n = fmaxf(m0, mx0), m1n = fmaxf(m1, mx1);
        float a0 = ex2(m0 - m0n),   a1 = ex2(m1 - m1n);
        m0 = m0n; m1 = m1n;

        float rs0 = 0.0f, rs1 = 0.0f;
#pragma unroll
        for (int nj = 0; nj < 8; nj++) {
            float p;
            p = ex2(s[nj][0] - m0n); rs0 += p; s[nj][0] = p;
            p = ex2(s[nj][1] - m0n); rs0 += p; s[nj][1] = p;
            p = ex2(s[nj][2] - m1n); rs1 += p; s[nj][2] = p;
            p = ex2(s[nj][3] - m1n); rs1 += p; s[nj][3] = p;
        }
        rs0 += __shfl_xor_sync(0xffffffffu, rs0, 1);
        rs0 += __shfl_xor_sync(0xffffffffu, rs0, 2);
        rs1 += __shfl_xor_sync(0xffffffffu, rs1, 1);
        rs1 += __shfl_xor_sync(0xffffffffu, rs1, 2);

        l0 = l0 * a0 + rs0;
        l1 = l1 * a1 + rs1;
#pragma unroll
        for (int nj = 0; nj < 8; nj++) {
            o[nj][0] *= a0; o[nj][1] *= a0;
            o[nj][2] *= a1; o[nj][3] *= a1;
        }

#pragma unroll
        for (int nj = 0; nj < 8; nj++) {
            int cc = nj * 8 + 2 * t;
            *(__half2*)&QPs[wrow + g][cc]     = __floats2half2_rn(s[nj][0], s[nj][1]);
            *(__half2*)&QPs[wrow + g + 8][cc] = __floats2half2_rn(s[nj][2], s[nj][3]);
        }
        __syncwarp();

        unsigned v_base = cur ? v_lane1 : v_lane0;
#pragma unroll
        for (int ks = 0; ks < 4; ks++) {
            unsigned pf[4];
            ldsm_x4(pf, qp_lane + ks * 32);
#pragma unroll
            for (int nj = 0; nj < 8; nj++) {
                unsigned vf[2];
                ldsm_x2_trans(vf, v_base + (unsigned)(ks * 16 * AR + nj * 8) * 2u);
                mma_f16(o[nj], pf, vf);
            }
        }
    }

    float inv0 = 1.0f / l0, inv1 = 1.0f / l1;
    int row0 = qb * 64 + wrow + g;
    size_t base0 = ((size_t)(b * SS + row0)) * DD + h * 64;
    size_t base1 = base0 + (size_t)8 * DD;
#pragma unroll
    for (int nj = 0; nj < 8; nj++) {
        int cc = nj * 8 + 2 * t;
        *(__half2*)&g_Ctxh[base0 + cc] = __floats2half2_rn(o[nj][0] * inv0, o[nj][1] * inv0);
        *(__half2*)&g_Ctxh[base1 + cc] = __floats2half2_rn(o[nj][2] * inv1, o[nj][3] * inv1);
    }
}

// ---------------------------------------------------------------------------
// kernel_launch
// ---------------------------------------------------------------------------
extern "C" void kernel_launch(void* const* d_in, const int* in_sizes, int n_in,
                              void* d_out, int out_size)
{
    const float* q    = (const float*)d_in[0];
    const float* k    = (const float*)d_in[1];
    const float* v    = (const float*)d_in[2];
    const float* wq_w = (const float*)d_in[4];
    const float* wq_b = (const float*)d_in[5];
    const float* wk_w = (const float*)d_in[6];
    const float* wk_b = (const float*)d_in[7];
    const float* wv_w = (const float*)d_in[8];
    const float* wv_b = (const float*)d_in[9];
    const float* wo_w = (const float*)d_in[10];
    const float* wo_b = (const float*)d_in[11];
    float* out = (float*)d_out;

    void *p_qh, *p_kh, *p_vh, *p_wh, *p_ctxh;
    cudaGetSymbolAddress(&p_qh, g_qh);
    cudaGetSymbolAddress(&p_kh, g_kh);
    cudaGetSymbolAddress(&p_vh, g_vh);
    cudaGetSymbolAddress(&p_wh, g_wh);
    cudaGetSymbolAddress(&p_ctxh, g_Ctxh);
    __half* w0 = (__half*)p_wh;
    __half* w1 = w0 + DD * DD;
    __half* w2 = w0 + 2 * DD * DD;
    __half* w3 = w0 + 3 * DD * DD;

    // prepass: convert inputs + weights to fp16
    F2HArgs fa;
    fa.src[0] = (const float4*)q;    fa.dst[0] = (__half*)p_qh; fa.n8[0] = MM * DD / 8;
    fa.src[1] = (const float4*)k;    fa.dst[1] = (__half*)p_kh; fa.n8[1] = MM * DD / 8;
    fa.src[2] = (const float4*)v;    fa.dst[2] = (__half*)p_vh; fa.n8[2] = MM * DD / 8;
    fa.src[3] = (const float4*)wq_w; fa.dst[3] = w0;            fa.n8[3] = DD * DD / 8;
    fa.src[4] = (const float4*)wk_w; fa.dst[4] = w1;            fa.n8[4] = DD * DD / 8;
    fa.src[5] = (const float4*)wv_w; fa.dst[5] = w2;            fa.n8[5] = DD * DD / 8;
    fa.src[6] = (const float4*)wo_w; fa.dst[6] = w3;            fa.n8[6] = DD * DD / 8;
    f2h_kernel<<<dim3(128, 1, 7), 256>>>(fa);

    // fused QKV projections (fp16 MMA, 64x64 warp tiles)
    GemmArgs qkv;
    qkv.A[0] = (const __half*)p_qh; qkv.A[1] = (const __half*)p_kh; qkv.A[2] = (const __half*)p_vh;
    qkv.W[0] = w0; qkv.W[1] = w1; qkv.W[2] = w2;
    qkv.bias[0] = wq_b; qkv.bias[1] = wk_b; qkv.bias[2] = wv_b;
    qkv.C = nullptr;
    qkv.out_mode[0] = 1; qkv.out_mode[1] = 2; qkv.out_mode[2] = 3;
    gemm_f16_kernel<<<dim3(DD / 128, MM / 128, 3), 128>>>(qkv);

    // attention
    attn_f16_kernel<<<dim3(SS / 64, BB * HH), 128>>>();

    // output projection (A = g_Ctxh fp16)
    GemmArgs og;
    og.A[0] = (const __half*)p_ctxh; og.A[1] = og.A[0]; og.A[2] = og.A[0];
    og.W[0] = w3; og.W[1] = w3; og.W[2] = w3;
    og.bias[0] = wo_b; og.bias[1] = wo_b; og.bias[2] = wo_b;
    og.C = out;
    og.out_mode[0] = 0; og.out_mode[1] = 0; og.out_mode[2] = 0;
    gemm_f16_kernel<<<dim3(DD / 128, MM / 128, 1), 128>>>(og);
}